// round 11
// baseline (speedup 1.0000x reference)
#include <cuda_runtime.h>
#include <cuda_fp16.h>
#include <cstdint>

#define NMAX 1000000
#define NE 4
#define DD 128
#define HH 128

#define LDS_F 132   // staging fp32 stride (words): 132 % 32 == 4

// scratch (no allocation allowed -> device globals)
__device__ int g_cursor[NE];
__device__ int g_sorted[NE * NMAX];

// ============================ helpers ============================
__device__ __forceinline__ uint32_t smem_u32(const void* p){
    uint32_t r;
    asm("{ .reg .u64 t; cvta.to.shared.u64 t, %1; cvt.u32.u64 %0, t; }" : "=r"(r) : "l"(p));
    return r;
}
__device__ __forceinline__ uint32_t pack_f16x2(float lo, float hi){
    uint32_t r;
    asm("cvt.rn.f16x2.f32 %0, %1, %2;" : "=r"(r) : "f"(hi), "f"(lo));
    return r;
}
__device__ __forceinline__ void cp_async16(uint32_t daddr, const void* src){
    asm volatile("cp.async.cg.shared.global [%0], [%1], 16;" :: "r"(daddr), "l"(src) : "memory");
}
#define CP_COMMIT() asm volatile("cp.async.commit_group;" ::: "memory")
#define CP_WAIT0()  asm volatile("cp.async.wait_group 0;"  ::: "memory")

__device__ __forceinline__ void mma_f16(float c[4],
                                        uint32_t a0, uint32_t a1, uint32_t a2, uint32_t a3,
                                        uint32_t b0, uint32_t b1){
    asm volatile(
        "mma.sync.aligned.m16n8k16.row.col.f32.f16.f16.f32 "
        "{%0,%1,%2,%3}, {%4,%5,%6,%7}, {%8,%9}, {%0,%1,%2,%3};"
        : "+f"(c[0]), "+f"(c[1]), "+f"(c[2]), "+f"(c[3])
        : "r"(a0), "r"(a1), "r"(a2), "r"(a3), "r"(b0), "r"(b1));
}

// ============================ bucketing ============================
__global__ void assign_kernel(const int* __restrict__ element, int n){
    __shared__ int wcnt[8][NE];
    __shared__ int woff[8][NE];
    __shared__ int bbase[NE];
    int tid = threadIdx.x, lane = tid & 31, w = tid >> 5;
    int i = blockIdx.x * 256 + tid;
    int e = (i < n) ? element[i] : -1;
    int rank = 0;
    #pragma unroll
    for (int ee = 0; ee < NE; ee++){
        unsigned m = __ballot_sync(0xFFFFFFFFu, e == ee);
        if (lane == 0) wcnt[w][ee] = __popc(m);
        if (e == ee) rank = __popc(m & ((1u << lane) - 1u));
    }
    __syncthreads();
    if (tid < NE){
        int s = 0;
        #pragma unroll
        for (int ww = 0; ww < 8; ww++){ int c = wcnt[ww][tid]; woff[ww][tid] = s; s += c; }
        bbase[tid] = s ? atomicAdd(&g_cursor[tid], s) : 0;
    }
    __syncthreads();
    if (e >= 0){
        int slot = bbase[e] + woff[w][e] + rank;
        g_sorted[e * NMAX + slot] = i;
    }
}

// ============================ main GEMM (fp16 MMA, fp32 accum) ============
__global__ __launch_bounds__(512, 1)
void gemm_kernel(const float* __restrict__ desc,
                 const float* __restrict__ W1,
                 const float* __restrict__ b1,
                 const float* __restrict__ W2,
                 const float* __restrict__ b2,
                 float* __restrict__ out)
{
    extern __shared__ float dyn[];
    float*    sStg = dyn;                              // [128 x LDS_F] fp32 staging (single)
    uint32_t* sAh  = (uint32_t*)(dyn + 128 * LDS_F);   // 2 x [128 x 68] f16x2 words
    uint4*    sBq  = (uint4*)(sAh + 2 * 128 * 68);     // packed B f16 quads (2048 uint4)

    __shared__ int   s_idx[2][128];
    __shared__ float s_part[128][4];
    __shared__ float s_b1e[HH], s_w2e[HH];
    __shared__ float s_b2e;
    __shared__ int   s_cnt[NE], s_tstart[NE + 1];

    const int tid  = threadIdx.x;
    const int wid  = tid >> 5;
    const int lane = tid & 31;
    const int l4   = lane >> 2;   // groupID (0..7)
    const int lm4  = lane & 3;    // threadID in group
    const int wm   = wid & 3;     // M group (32 rows)
    const int wn   = wid >> 2;    // N group (32 cols)

    if (tid == 0){
        int s = 0;
        s_tstart[0] = 0;
        #pragma unroll
        for (int e = 0; e < NE; e++){
            int c = g_cursor[e];
            s_cnt[e] = c;
            s += (c + 127) >> 7;
            s_tstart[e + 1] = s;
        }
    }
    __syncthreads();

    const int total = s_tstart[NE];
    const int chunk = (total + (int)gridDim.x - 1) / (int)gridDim.x;
    const int t0 = blockIdx.x * chunk;
    const int t1 = min(total, t0 + chunk);

    if (t0 < t1) {
        auto expert_of = [&](int t){ int e = 0; while (t >= s_tstart[e + 1]) e++; return e; };

        // persistent per-expert B fragments: 16 uint4 = 64 regs/lane
        uint4 breg[16];
        const int innerB = ((l4 >> 1) << 3) + (lm4 << 1) + (l4 & 1);

        auto load_expert = [&](int e){
            const float* W1e = W1 + (size_t)e * DD * HH;
            __half* sBh = (__half*)sBq;
            for (int v = tid; v < DD * HH; v += 512){
                int k = v >> 7, col = v & 127;       // W1[e][k][col]
                int ks = k >> 4, kk = k & 15;
                int lm4b = (kk & 7) >> 1, ddb = kk & 1, hb = kk >> 3;
                int wnb = col >> 5, rem = col & 31;
                int nbb = rem >> 3, l4b = rem & 7;
                int q = nbb >> 1, slot = (nbb & 1) * 2 + hb;
                int inner = ((l4b >> 1) << 3) + (lm4b << 1) + (l4b & 1);   // 0..31 bijection
                int idx128 = ((ks * 4 + wnb) * 2 + q) * 32 + inner;
                sBh[idx128 * 8 + slot * 2 + ddb] = __float2half_rn(W1e[v]);
            }
            if (tid < HH){
                s_b1e[tid] = b1[e * HH + tid];
                s_w2e[tid] = W2[e * HH + tid];
            }
            if (tid == 0) s_b2e = b2[e];
            __syncthreads();
            // hoist this warp's B fragments into registers for the whole expert run
            #pragma unroll
            for (int ks = 0; ks < 8; ks++){
                breg[ks * 2 + 0] = sBq[((ks * 4 + wn) * 2 + 0) * 32 + innerB];
                breg[ks * 2 + 1] = sBq[((ks * 4 + wn) * 2 + 1) * 32 + innerB];
            }
        };

        auto gather = [&](int t, int e, int buf){
            int trow = (t - s_tstart[e]) << 7;
            int rows = min(128, s_cnt[e] - trow);
            const int* bidx = g_sorted + e * NMAX + trow;
            if (tid < 128) s_idx[buf][tid] = (tid < rows) ? bidx[tid] : -1;
            #pragma unroll 8
            for (int v = tid; v < 128 * 32; v += 512){
                int row = v >> 5, seg = v & 31;
                float* dst = sStg + row * LDS_F + seg * 4;
                if (row < rows){
                    int a = __ldg(bidx + row);
                    cp_async16(smem_u32(dst), desc + (size_t)a * DD + seg * 4);
                } else {
                    *(float4*)dst = make_float4(0.f, 0.f, 0.f, 0.f);
                }
            }
            CP_COMMIT();
        };

        // staging fp32 -> f16x2 words in sAh[buf] (rn conversion)
        auto convert = [&](int buf){
            uint32_t* Ah = sAh + buf * (128 * 68);
            #pragma unroll 8
            for (int v = tid; v < 128 * 32; v += 512){
                int row = v >> 5, seg = v & 31;
                float4 f = *(const float4*)(sStg + row * LDS_F + seg * 4);
                uint32_t lo = pack_f16x2(f.x, f.y);
                uint32_t hi = pack_f16x2(f.z, f.w);
                uint2* dst = (uint2*)(Ah + row * 68 + seg * 2);
                *dst = make_uint2(lo, hi);
            }
        };

        int cur_e = expert_of(t0);
        load_expert(cur_e);
        gather(t0, cur_e, 0);
        CP_WAIT0();
        __syncthreads();
        convert(0);
        __syncthreads();

        for (int t = t0; t < t1; ++t){
            const int buf = (t - t0) & 1;

            // prefetch next tile into staging (async during MMA)
            const int tn = t + 1;
            const bool have_next = tn < t1;
            const int e_next = have_next ? expert_of(tn) : -1;
            const bool same = have_next && (e_next == cur_e);
            if (same) gather(tn, cur_e, buf ^ 1);

            // ---- MMA: D[128x128] = A[128x128] @ W1^T (f16, B in registers) ----
            float acc[2][4][4];
            #pragma unroll
            for (int mb = 0; mb < 2; mb++)
                #pragma unroll
                for (int nb = 0; nb < 4; nb++)
                    #pragma unroll
                    for (int i = 0; i < 4; i++) acc[mb][nb][i] = 0.f;

            const uint32_t* Ah = sAh + buf * (128 * 68);

            #pragma unroll
            for (int ks = 0; ks < 8; ks++){     // k16 per step; MUST stay fully unrolled
                uint32_t a[2][4];
                #pragma unroll
                for (int mb = 0; mb < 2; mb++){
                    const uint32_t* ap = Ah + (32 * wm + 16 * mb + l4) * 68 + ks * 8 + lm4;
                    a[mb][0] = ap[0];           // rows l4 / l4+8, k halves 2lm4.. / +8
                    a[mb][1] = ap[8 * 68];
                    a[mb][2] = ap[4];
                    a[mb][3] = ap[8 * 68 + 4];
                }
                const uint4 bq0 = breg[ks * 2 + 0];
                const uint4 bq1 = breg[ks * 2 + 1];
                #pragma unroll
                for (int mb = 0; mb < 2; mb++){
                    mma_f16(acc[mb][0], a[mb][0], a[mb][1], a[mb][2], a[mb][3], bq0.x, bq0.y);
                    mma_f16(acc[mb][1], a[mb][0], a[mb][1], a[mb][2], a[mb][3], bq0.z, bq0.w);
                    mma_f16(acc[mb][2], a[mb][0], a[mb][1], a[mb][2], a[mb][3], bq1.x, bq1.y);
                    mma_f16(acc[mb][3], a[mb][0], a[mb][1], a[mb][2], a[mb][3], bq1.z, bq1.w);
                }
            }

            // ---- epilogue: y[row] = sum_col relu(d + b1[col]) * w2[col] ----
            #pragma unroll
            for (int mb = 0; mb < 2; mb++){
                #pragma unroll
                for (int half = 0; half < 2; half++){
                    float p = 0.f;
                    #pragma unroll
                    for (int nb = 0; nb < 4; nb++){
                        int col = 32 * wn + 8 * nb + 2 * lm4;
                        float2 bb1 = *(const float2*)&s_b1e[col];
                        float2 ww2 = *(const float2*)&s_w2e[col];
                        float h0 = fmaxf(acc[mb][nb][2 * half + 0] + bb1.x, 0.f);
                        float h1 = fmaxf(acc[mb][nb][2 * half + 1] + bb1.y, 0.f);
                        p = fmaf(h0, ww2.x, p);
                        p = fmaf(h1, ww2.y, p);
                    }
                    p += __shfl_xor_sync(0xFFFFFFFFu, p, 1);
                    p += __shfl_xor_sync(0xFFFFFFFFu, p, 2);
                    if (lm4 == 0){
                        int row = 32 * wm + 16 * mb + 8 * half + l4;
                        s_part[row][wn] = p;
                    }
                }
            }
            __syncthreads();
            if (tid < 128){
                int a = s_idx[buf][tid];
                if (a >= 0)
                    out[a] = (s_part[tid][0] + s_part[tid][1])
                           + (s_part[tid][2] + s_part[tid][3]) + s_b2e;
            }

            if (have_next){
                if (!same){
                    __syncthreads();
                    cur_e = e_next;
                    load_expert(cur_e);
                    gather(tn, cur_e, buf ^ 1);
                }
                CP_WAIT0();
                __syncthreads();          // staging complete + epilogue reads done
                convert(buf ^ 1);
                __syncthreads();          // sAh[buf^1] ready for next MMA
            }
        }
    }

    // reset bucket cursors for the next replay (grid=148 is one wave, so all
    // CTAs snapshot g_cursor at entry before block 0 finishes)
    if (blockIdx.x == 0 && threadIdx.x < NE) g_cursor[threadIdx.x] = 0;
}

// ============================ launch ============================
extern "C" void kernel_launch(void* const* d_in, const int* in_sizes, int n_in,
                              void* d_out, int out_size)
{
    const int*   element = (const int*)d_in[0];
    const float* desc    = (const float*)d_in[1];
    const float* W1      = (const float*)d_in[2];
    const float* b1      = (const float*)d_in[3];
    const float* W2      = (const float*)d_in[4];
    const float* b2      = (const float*)d_in[5];
    float* out = (float*)d_out;
    int n = in_sizes[0];

    // staging 128*132*4 + A-f16 2*128*68*4 + B-f16 2048*16 = 67584+69632+32768
    const int DYN = 128 * LDS_F * 4 + 2 * 128 * 68 * 4 + 2048 * 16;  // 169984 B
    cudaFuncSetAttribute(gemm_kernel, cudaFuncAttributeMaxDynamicSharedMemorySize, DYN);

    assign_kernel<<<(n + 255) / 256, 256>>>(element, n);
    gemm_kernel<<<148, 512, DYN>>>(desc, W1, b1, W2, b2, out);
}

// round 12
// speedup vs baseline: 1.0327x; 1.0327x over previous
#include <cuda_runtime.h>
#include <cuda_fp16.h>
#include <cstdint>

#define NMAX 1000000
#define NE 4
#define DD 128
#define HH 128

#define LDS_F 132   // staging fp32 stride (words): 132 % 32 == 4

// scratch (no allocation allowed -> device globals)
__device__ int g_cursor[NE];
__device__ int g_sorted[NE * NMAX];

// ============================ helpers ============================
__device__ __forceinline__ uint32_t smem_u32(const void* p){
    uint32_t r;
    asm("{ .reg .u64 t; cvta.to.shared.u64 t, %1; cvt.u32.u64 %0, t; }" : "=r"(r) : "l"(p));
    return r;
}
__device__ __forceinline__ uint32_t pack_f16x2(float lo, float hi){
    uint32_t r;
    asm("cvt.rn.f16x2.f32 %0, %1, %2;" : "=r"(r) : "f"(hi), "f"(lo));
    return r;
}
__device__ __forceinline__ void cp_async16(uint32_t daddr, const void* src){
    asm volatile("cp.async.cg.shared.global [%0], [%1], 16;" :: "r"(daddr), "l"(src) : "memory");
}
#define CP_COMMIT() asm volatile("cp.async.commit_group;" ::: "memory")
#define CP_WAIT0()  asm volatile("cp.async.wait_group 0;"  ::: "memory")

__device__ __forceinline__ void mma_f16(float c[4],
                                        uint32_t a0, uint32_t a1, uint32_t a2, uint32_t a3,
                                        uint32_t b0, uint32_t b1){
    asm volatile(
        "mma.sync.aligned.m16n8k16.row.col.f32.f16.f16.f32 "
        "{%0,%1,%2,%3}, {%4,%5,%6,%7}, {%8,%9}, {%0,%1,%2,%3};"
        : "+f"(c[0]), "+f"(c[1]), "+f"(c[2]), "+f"(c[3])
        : "r"(a0), "r"(a1), "r"(a2), "r"(a3), "r"(b0), "r"(b1));
}

// ============================ bucketing ============================
__global__ void assign_kernel(const int* __restrict__ element, int n){
    __shared__ int wcnt[8][NE];
    __shared__ int woff[8][NE];
    __shared__ int bbase[NE];
    int tid = threadIdx.x, lane = tid & 31, w = tid >> 5;
    int i = blockIdx.x * 256 + tid;
    int e = (i < n) ? element[i] : -1;
    int rank = 0;
    #pragma unroll
    for (int ee = 0; ee < NE; ee++){
        unsigned m = __ballot_sync(0xFFFFFFFFu, e == ee);
        if (lane == 0) wcnt[w][ee] = __popc(m);
        if (e == ee) rank = __popc(m & ((1u << lane) - 1u));
    }
    __syncthreads();
    if (tid < NE){
        int s = 0;
        #pragma unroll
        for (int ww = 0; ww < 8; ww++){ int c = wcnt[ww][tid]; woff[ww][tid] = s; s += c; }
        bbase[tid] = s ? atomicAdd(&g_cursor[tid], s) : 0;
    }
    __syncthreads();
    if (e >= 0){
        int slot = bbase[e] + woff[w][e] + rank;
        g_sorted[e * NMAX + slot] = i;
    }
}

// ============================ main GEMM (fp16 MMA, fp32 accum) ============
__global__ __launch_bounds__(512, 1)
void gemm_kernel(const float* __restrict__ desc,
                 const float* __restrict__ W1,
                 const float* __restrict__ b1,
                 const float* __restrict__ W2,
                 const float* __restrict__ b2,
                 float* __restrict__ out)
{
    extern __shared__ float dyn[];
    float*    sStg = dyn;                              // [128 x LDS_F] fp32 staging (single)
    uint32_t* sAh  = (uint32_t*)(dyn + 128 * LDS_F);   // 2 x [128 x 68] f16x2 words
    float4*   sBq  = (float4*)(sAh + 2 * 128 * 68);    // packed B f16 quads (2048 float4)

    __shared__ int   s_idx[2][128];
    __shared__ float s_part[128][4];
    __shared__ float s_b1e[HH], s_w2e[HH];
    __shared__ float s_b2e;

    const int tid  = threadIdx.x;
    const int wid  = tid >> 5;
    const int lane = tid & 31;
    const int l4   = lane >> 2;   // groupID (0..7)
    const int lm4  = lane & 3;    // threadID in group
    const int wm   = wid & 3;     // M group (32 rows)
    const int wn   = wid >> 2;    // N group (32 cols)

    int cnt[NE], tstart[NE + 1];
    tstart[0] = 0;
    #pragma unroll
    for (int e = 0; e < NE; e++){
        cnt[e] = g_cursor[e];
        tstart[e + 1] = tstart[e] + ((cnt[e] + 127) >> 7);
    }
    const int total = tstart[NE];
    const int chunk = (total + (int)gridDim.x - 1) / (int)gridDim.x;
    const int t0 = blockIdx.x * chunk;
    const int t1 = min(total, t0 + chunk);

    if (t0 < t1) {
        auto expert_of = [&](int t){ int e = 0; while (t >= tstart[e + 1]) e++; return e; };

        auto load_expert = [&](int e){
            const float* W1e = W1 + (size_t)e * DD * HH;
            __half* sBh = (__half*)sBq;
            for (int v = tid; v < DD * HH; v += 512){
                int k = v >> 7, col = v & 127;       // W1[e][k][col]
                int ks = k >> 4, kk = k & 15;
                int lm4b = (kk & 7) >> 1, ddb = kk & 1, hb = kk >> 3;
                int wnb = col >> 5, rem = col & 31;
                int nbb = rem >> 3, l4b = rem & 7;
                int q = nbb >> 1, slot = (nbb & 1) * 2 + hb;
                int inner = ((l4b >> 1) << 3) + (lm4b << 1) + (l4b & 1);   // 0..31 bijection
                int idx128 = ((ks * 4 + wnb) * 2 + q) * 32 + inner;
                sBh[idx128 * 8 + slot * 2 + ddb] = __float2half_rn(W1e[v]);
            }
            if (tid < HH){
                s_b1e[tid] = b1[e * HH + tid];
                s_w2e[tid] = W2[e * HH + tid];
            }
            if (tid == 0) s_b2e = b2[e];
        };

        auto gather = [&](int t, int e, int buf){
            int trow = (t - tstart[e]) << 7;
            int rows = min(128, cnt[e] - trow);
            const int* bidx = g_sorted + e * NMAX + trow;
            if (tid < 128) s_idx[buf][tid] = (tid < rows) ? bidx[tid] : -1;
            #pragma unroll 8
            for (int v = tid; v < 128 * 32; v += 512){
                int row = v >> 5, seg = v & 31;
                float* dst = sStg + row * LDS_F + seg * 4;
                if (row < rows){
                    int a = __ldg(bidx + row);
                    cp_async16(smem_u32(dst), desc + (size_t)a * DD + seg * 4);
                } else {
                    *(float4*)dst = make_float4(0.f, 0.f, 0.f, 0.f);
                }
            }
            CP_COMMIT();
        };

        // staging fp32 -> f16x2 words in sAh[buf] (rn conversion).
        // NOTE: indexes with the SAME v = tid + i*512 pattern as gather, so each
        // thread converts exactly the bytes its own cp.asyncs wrote -> after
        // CP_WAIT0 no __syncthreads is needed before converting.
        auto convert = [&](int buf){
            uint32_t* Ah = sAh + buf * (128 * 68);
            #pragma unroll 8
            for (int v = tid; v < 128 * 32; v += 512){
                int row = v >> 5, seg = v & 31;
                float4 f = *(const float4*)(sStg + row * LDS_F + seg * 4);
                uint32_t lo = pack_f16x2(f.x, f.y);
                uint32_t hi = pack_f16x2(f.z, f.w);
                uint2* dst = (uint2*)(Ah + row * 68 + seg * 2);
                *dst = make_uint2(lo, hi);
            }
        };

        int cur_e = expert_of(t0);
        load_expert(cur_e);
        gather(t0, cur_e, 0);
        CP_WAIT0();
        convert(0);
        __syncthreads();

        for (int t = t0; t < t1; ++t){
            const int buf = (t - t0) & 1;

            // prefetch next tile into staging (async during first half of MMA)
            const int tn = t + 1;
            const bool have_next = tn < t1;
            const int e_next = have_next ? expert_of(tn) : -1;
            const bool same = have_next && (e_next == cur_e);
            if (same) gather(tn, cur_e, buf ^ 1);

            // ---- MMA: D[128x128] = A[128x128] @ W1^T (f16 operands) ----
            float acc[2][4][4];
            #pragma unroll
            for (int mb = 0; mb < 2; mb++)
                #pragma unroll
                for (int nb = 0; nb < 4; nb++)
                    #pragma unroll
                    for (int i = 0; i < 4; i++) acc[mb][nb][i] = 0.f;

            const uint32_t* Ah = sAh + buf * (128 * 68);
            const int innerB = ((l4 >> 1) << 3) + (lm4 << 1) + (l4 & 1);

            auto mma_step = [&](int ks){
                uint32_t a[2][4];
                #pragma unroll
                for (int mb = 0; mb < 2; mb++){
                    const uint32_t* ap = Ah + (32 * wm + 16 * mb + l4) * 68 + ks * 8 + lm4;
                    a[mb][0] = ap[0];
                    a[mb][1] = ap[8 * 68];
                    a[mb][2] = ap[4];
                    a[mb][3] = ap[8 * 68 + 4];
                }
                uint32_t b[4][2];
                const float4* bp = sBq + ((ks * 4 + wn) * 2) * 32 + innerB;
                float4 bq0 = bp[0];
                float4 bq1 = bp[32];
                b[0][0] = __float_as_uint(bq0.x); b[0][1] = __float_as_uint(bq0.y);
                b[1][0] = __float_as_uint(bq0.z); b[1][1] = __float_as_uint(bq0.w);
                b[2][0] = __float_as_uint(bq1.x); b[2][1] = __float_as_uint(bq1.y);
                b[3][0] = __float_as_uint(bq1.z); b[3][1] = __float_as_uint(bq1.w);
                #pragma unroll
                for (int mb = 0; mb < 2; mb++)
                    #pragma unroll
                    for (int nb = 0; nb < 4; nb++)
                        mma_f16(acc[mb][nb], a[mb][0], a[mb][1], a[mb][2], a[mb][3],
                                b[nb][0], b[nb][1]);
            };

            // first half of k
            #pragma unroll
            for (int ks = 0; ks < 4; ks++) mma_step(ks);

            // hidden convert: per-thread wait on own cp.asyncs, then convert —
            // overlaps the tensor pipe (no barrier; pattern-matched with gather)
            if (same){
                CP_WAIT0();
                convert(buf ^ 1);
            }

            // second half of k
            #pragma unroll
            for (int ks = 4; ks < 8; ks++) mma_step(ks);

            // ---- epilogue: y[row] = sum_col relu(d + b1[col]) * w2[col] ----
            #pragma unroll
            for (int mb = 0; mb < 2; mb++){
                #pragma unroll
                for (int half = 0; half < 2; half++){
                    float p = 0.f;
                    #pragma unroll
                    for (int nb = 0; nb < 4; nb++){
                        int col = 32 * wn + 8 * nb + 2 * lm4;
                        float2 bb1 = *(const float2*)&s_b1e[col];
                        float2 ww2 = *(const float2*)&s_w2e[col];
                        float h0 = fmaxf(acc[mb][nb][2 * half + 0] + bb1.x, 0.f);
                        float h1 = fmaxf(acc[mb][nb][2 * half + 1] + bb1.y, 0.f);
                        p = fmaf(h0, ww2.x, p);
                        p = fmaf(h1, ww2.y, p);
                    }
                    p += __shfl_xor_sync(0xFFFFFFFFu, p, 1);
                    p += __shfl_xor_sync(0xFFFFFFFFu, p, 2);
                    if (lm4 == 0){
                        int row = 32 * wm + 16 * mb + 8 * half + l4;
                        s_part[row][wn] = p;
                    }
                }
            }
            __syncthreads();   // s_part ready; also publishes all converts of buf^1
            if (tid < 128){
                int a = s_idx[buf][tid];
                if (a >= 0)
                    out[a] = (s_part[tid][0] + s_part[tid][1])
                           + (s_part[tid][2] + s_part[tid][3]) + s_b2e;
            }

            if (have_next && !same){
                // expert switch (rare): all warps past MMA after the sync below
                __syncthreads();
                cur_e = e_next;
                load_expert(cur_e);
                gather(tn, cur_e, buf ^ 1);
                CP_WAIT0();
                convert(buf ^ 1);
            }
            __syncthreads();   // protect s_part & s_idx[buf] reuse next tile
        }
    }

    // reset bucket cursors for the next replay (grid=148 is one wave, so all
    // CTAs snapshot g_cursor at entry before block 0 finishes)
    if (blockIdx.x == 0 && threadIdx.x < NE) g_cursor[threadIdx.x] = 0;
}

// ============================ launch ============================
extern "C" void kernel_launch(void* const* d_in, const int* in_sizes, int n_in,
                              void* d_out, int out_size)
{
    const int*   element = (const int*)d_in[0];
    const float* desc    = (const float*)d_in[1];
    const float* W1      = (const float*)d_in[2];
    const float* b1      = (const float*)d_in[3];
    const float* W2      = (const float*)d_in[4];
    const float* b2      = (const float*)d_in[5];
    float* out = (float*)d_out;
    int n = in_sizes[0];

    // staging 128*132*4 + A-f16 2*128*68*4 + B-f16 2048*16 = 67584+69632+32768
    const int DYN = 128 * LDS_F * 4 + 2 * 128 * 68 * 4 + 2048 * 16;  // 169984 B
    cudaFuncSetAttribute(gemm_kernel, cudaFuncAttributeMaxDynamicSharedMemorySize, DYN);

    assign_kernel<<<(n + 255) / 256, 256>>>(element, n);
    gemm_kernel<<<148, 512, DYN>>>(desc, W1, b1, W2, b2, out);
}

// round 13
// speedup vs baseline: 1.0621x; 1.0285x over previous
#include <cuda_runtime.h>
#include <cuda_fp16.h>
#include <cstdint>

#define NMAX 1000000
#define NE 4
#define DD 128
#define HH 128

#define LDS_F 132   // staging fp32 stride (words): 132 % 32 == 4

// scratch (no allocation allowed -> device globals)
__device__ int g_cursor[NE];
__device__ int g_sorted[NE * NMAX];

// ============================ helpers ============================
__device__ __forceinline__ uint32_t smem_u32(const void* p){
    uint32_t r;
    asm("{ .reg .u64 t; cvta.to.shared.u64 t, %1; cvt.u32.u64 %0, t; }" : "=r"(r) : "l"(p));
    return r;
}
__device__ __forceinline__ uint32_t pack_f16x2(float lo, float hi){
    uint32_t r;
    asm("cvt.rn.f16x2.f32 %0, %1, %2;" : "=r"(r) : "f"(hi), "f"(lo));
    return r;
}
__device__ __forceinline__ void cp_async16(uint32_t daddr, const void* src){
    asm volatile("cp.async.cg.shared.global [%0], [%1], 16;" :: "r"(daddr), "l"(src) : "memory");
}
#define CP_COMMIT() asm volatile("cp.async.commit_group;" ::: "memory")
#define CP_WAIT0()  asm volatile("cp.async.wait_group 0;"  ::: "memory")

__device__ __forceinline__ void ldsm_x4(uint32_t& r0, uint32_t& r1, uint32_t& r2, uint32_t& r3,
                                        uint32_t addr){
    asm volatile("ldmatrix.sync.aligned.m8n8.x4.shared.b16 {%0,%1,%2,%3}, [%4];"
        : "=r"(r0), "=r"(r1), "=r"(r2), "=r"(r3) : "r"(addr));
}
__device__ __forceinline__ void mma_f16(float c[4],
                                        uint32_t a0, uint32_t a1, uint32_t a2, uint32_t a3,
                                        uint32_t b0, uint32_t b1){
    asm volatile(
        "mma.sync.aligned.m16n8k16.row.col.f32.f16.f16.f32 "
        "{%0,%1,%2,%3}, {%4,%5,%6,%7}, {%8,%9}, {%0,%1,%2,%3};"
        : "+f"(c[0]), "+f"(c[1]), "+f"(c[2]), "+f"(c[3])
        : "r"(a0), "r"(a1), "r"(a2), "r"(a3), "r"(b0), "r"(b1));
}

// ============================ bucketing ============================
__global__ void assign_kernel(const int* __restrict__ element, int n){
    __shared__ int wcnt[8][NE];
    __shared__ int woff[8][NE];
    __shared__ int bbase[NE];
    int tid = threadIdx.x, lane = tid & 31, w = tid >> 5;
    int i = blockIdx.x * 256 + tid;
    int e = (i < n) ? element[i] : -1;
    int rank = 0;
    #pragma unroll
    for (int ee = 0; ee < NE; ee++){
        unsigned m = __ballot_sync(0xFFFFFFFFu, e == ee);
        if (lane == 0) wcnt[w][ee] = __popc(m);
        if (e == ee) rank = __popc(m & ((1u << lane) - 1u));
    }
    __syncthreads();
    if (tid < NE){
        int s = 0;
        #pragma unroll
        for (int ww = 0; ww < 8; ww++){ int c = wcnt[ww][tid]; woff[ww][tid] = s; s += c; }
        bbase[tid] = s ? atomicAdd(&g_cursor[tid], s) : 0;
    }
    __syncthreads();
    if (e >= 0){
        int slot = bbase[e] + woff[w][e] + rank;
        g_sorted[e * NMAX + slot] = i;
    }
}

// ============================ main GEMM (fp16 MMA, fp32 accum) ============
__global__ __launch_bounds__(512, 1)
void gemm_kernel(const float* __restrict__ desc,
                 const float* __restrict__ W1,
                 const float* __restrict__ b1,
                 const float* __restrict__ W2,
                 const float* __restrict__ b2,
                 float* __restrict__ out)
{
    extern __shared__ float dyn[];
    float*    sStg = dyn;                              // [128 x LDS_F] fp32 staging (single)
    uint32_t* sAh  = (uint32_t*)(dyn + 128 * LDS_F);   // 2 x [128 x 68] f16x2 words
    float4*   sBq  = (float4*)(sAh + 2 * 128 * 68);    // packed B f16 quads (2048 float4)

    __shared__ int   s_idx[2][128];
    __shared__ float s_part[2][128][4];                // double-buffered: kills trailing barrier
    __shared__ float s_b1e[HH], s_w2e[HH];
    __shared__ float s_b2e;

    const int tid  = threadIdx.x;
    const int wid  = tid >> 5;
    const int lane = tid & 31;
    const int l4   = lane >> 2;   // groupID (0..7)
    const int lm4  = lane & 3;    // threadID in group
    const int wm   = wid & 3;     // M group (32 rows)
    const int wn   = wid >> 2;    // N group (32 cols)

    int cnt[NE], tstart[NE + 1];
    tstart[0] = 0;
    #pragma unroll
    for (int e = 0; e < NE; e++){
        cnt[e] = g_cursor[e];
        tstart[e + 1] = tstart[e] + ((cnt[e] + 127) >> 7);
    }
    const int total = tstart[NE];
    const int chunk = (total + (int)gridDim.x - 1) / (int)gridDim.x;
    const int t0 = blockIdx.x * chunk;
    const int t1 = min(total, t0 + chunk);

    if (t0 < t1) {
        auto expert_of = [&](int t){ int e = 0; while (t >= tstart[e + 1]) e++; return e; };

        auto load_expert = [&](int e){
            const float* W1e = W1 + (size_t)e * DD * HH;
            __half* sBh = (__half*)sBq;
            for (int v = tid; v < DD * HH; v += 512){
                int k = v >> 7, col = v & 127;       // W1[e][k][col]
                int ks = k >> 4, kk = k & 15;
                int lm4b = (kk & 7) >> 1, ddb = kk & 1, hb = kk >> 3;
                int wnb = col >> 5, rem = col & 31;
                int nbb = rem >> 3, l4b = rem & 7;
                int q = nbb >> 1, slot = (nbb & 1) * 2 + hb;
                int inner = ((l4b >> 1) << 3) + (lm4b << 1) + (l4b & 1);   // 0..31 bijection
                int idx128 = ((ks * 4 + wnb) * 2 + q) * 32 + inner;
                sBh[idx128 * 8 + slot * 2 + ddb] = __float2half_rn(W1e[v]);
            }
            if (tid < HH){
                s_b1e[tid] = b1[e * HH + tid];
                s_w2e[tid] = W2[e * HH + tid];
            }
            if (tid == 0) s_b2e = b2[e];
        };

        auto gather = [&](int t, int e, int buf){
            int trow = (t - tstart[e]) << 7;
            int rows = min(128, cnt[e] - trow);
            const int* bidx = g_sorted + e * NMAX + trow;
            if (tid < 128) s_idx[buf][tid] = (tid < rows) ? bidx[tid] : -1;
            #pragma unroll 8
            for (int v = tid; v < 128 * 32; v += 512){
                int row = v >> 5, seg = v & 31;
                float* dst = sStg + row * LDS_F + seg * 4;
                if (row < rows){
                    int a = __ldg(bidx + row);
                    cp_async16(smem_u32(dst), desc + (size_t)a * DD + seg * 4);
                } else {
                    *(float4*)dst = make_float4(0.f, 0.f, 0.f, 0.f);
                }
            }
            CP_COMMIT();
        };

        // staging fp32 -> f16x2 words in sAh[buf]. Same v-pattern as gather,
        // so CP_WAIT0 alone (no barrier) orders each thread's own bytes.
        auto convert = [&](int buf){
            uint32_t* Ah = sAh + buf * (128 * 68);
            #pragma unroll 8
            for (int v = tid; v < 128 * 32; v += 512){
                int row = v >> 5, seg = v & 31;
                float4 f = *(const float4*)(sStg + row * LDS_F + seg * 4);
                uint32_t lo = pack_f16x2(f.x, f.y);
                uint32_t hi = pack_f16x2(f.z, f.w);
                uint2* dst = (uint2*)(Ah + row * 68 + seg * 2);
                *dst = make_uint2(lo, hi);
            }
        };

        int cur_e = expert_of(t0);
        load_expert(cur_e);
        gather(t0, cur_e, 0);
        CP_WAIT0();
        convert(0);
        __syncthreads();

        // ldmatrix lane addressing: lane -> row (lane&15), k-half (lane>>4)
        const uint32_t aLane = (uint32_t)(((lane & 15) * 68 + ((lane >> 4) << 2)) << 2);
        const int innerB = ((l4 >> 1) << 3) + (lm4 << 1) + (l4 & 1);

        for (int t = t0; t < t1; ++t){
            const int buf = (t - t0) & 1;

            // prefetch next tile into staging (async during first half of MMA)
            const int tn = t + 1;
            const bool have_next = tn < t1;
            const int e_next = have_next ? expert_of(tn) : -1;
            const bool same = have_next && (e_next == cur_e);
            if (same) gather(tn, cur_e, buf ^ 1);

            // ---- MMA: D[128x128] = A[128x128] @ W1^T (f16 operands) ----
            float acc[2][4][4];
            #pragma unroll
            for (int mb = 0; mb < 2; mb++)
                #pragma unroll
                for (int nb = 0; nb < 4; nb++)
                    #pragma unroll
                    for (int i = 0; i < 4; i++) acc[mb][nb][i] = 0.f;

            const uint32_t* Ah = sAh + buf * (128 * 68);
            const uint32_t aBase0 = smem_u32(Ah) + (uint32_t)((32 * wm * 68) << 2) + aLane;
            const uint32_t aBase1 = aBase0 + (uint32_t)((16 * 68) << 2);

            auto mma_step = [&](int ks){
                uint32_t a[2][4];
                ldsm_x4(a[0][0], a[0][1], a[0][2], a[0][3], aBase0 + ks * 32);
                ldsm_x4(a[1][0], a[1][1], a[1][2], a[1][3], aBase1 + ks * 32);
                uint32_t b[4][2];
                const float4* bp = sBq + ((ks * 4 + wn) * 2) * 32 + innerB;
                float4 bq0 = bp[0];
                float4 bq1 = bp[32];
                b[0][0] = __float_as_uint(bq0.x); b[0][1] = __float_as_uint(bq0.y);
                b[1][0] = __float_as_uint(bq0.z); b[1][1] = __float_as_uint(bq0.w);
                b[2][0] = __float_as_uint(bq1.x); b[2][1] = __float_as_uint(bq1.y);
                b[3][0] = __float_as_uint(bq1.z); b[3][1] = __float_as_uint(bq1.w);
                #pragma unroll
                for (int mb = 0; mb < 2; mb++)
                    #pragma unroll
                    for (int nb = 0; nb < 4; nb++)
                        mma_f16(acc[mb][nb], a[mb][0], a[mb][1], a[mb][2], a[mb][3],
                                b[nb][0], b[nb][1]);
            };

            #pragma unroll
            for (int ks = 0; ks < 4; ks++) mma_step(ks);

            if (same){                 // hidden convert (per-thread ordering only)
                CP_WAIT0();
                convert(buf ^ 1);
            }

            #pragma unroll
            for (int ks = 4; ks < 8; ks++) mma_step(ks);

            // ---- epilogue: y[row] = sum_col relu(d + b1[col]) * w2[col] ----
            #pragma unroll
            for (int mb = 0; mb < 2; mb++){
                #pragma unroll
                for (int half = 0; half < 2; half++){
                    float p = 0.f;
                    #pragma unroll
                    for (int nb = 0; nb < 4; nb++){
                        int col = 32 * wn + 8 * nb + 2 * lm4;
                        float2 bb1 = *(const float2*)&s_b1e[col];
                        float2 ww2 = *(const float2*)&s_w2e[col];
                        float h0 = fmaxf(acc[mb][nb][2 * half + 0] + bb1.x, 0.f);
                        float h1 = fmaxf(acc[mb][nb][2 * half + 1] + bb1.y, 0.f);
                        p = fmaf(h0, ww2.x, p);
                        p = fmaf(h1, ww2.y, p);
                    }
                    p += __shfl_xor_sync(0xFFFFFFFFu, p, 1);
                    p += __shfl_xor_sync(0xFFFFFFFFu, p, 2);
                    if (lm4 == 0){
                        int row = 32 * wm + 16 * mb + 8 * half + l4;
                        s_part[buf][row][wn] = p;
                    }
                }
            }
            __syncthreads();   // single per-tile barrier: s_part[buf] + Ah[buf^1] published
            if (tid < 128){
                int a = s_idx[buf][tid];
                if (a >= 0)
                    out[a] = (s_part[buf][tid][0] + s_part[buf][tid][1])
                           + (s_part[buf][tid][2] + s_part[buf][tid][3]) + s_b2e;
            }
            // no trailing barrier: next tile uses s_part[buf^1]/s_idx[buf^1];
            // sStg/Ah hazards are ordered by the barrier above.

            if (have_next && !same){
                // expert switch (rare): protect sBq/s_b1e/s_w2e/s_b2e readers
                __syncthreads();
                cur_e = e_next;
                load_expert(cur_e);
                gather(tn, cur_e, buf ^ 1);
                CP_WAIT0();
                convert(buf ^ 1);
                __syncthreads();
            }
        }
    }

    // reset bucket cursors for the next replay (grid=148 is one wave, so all
    // CTAs snapshot g_cursor at entry before block 0 finishes)
    if (blockIdx.x == 0 && threadIdx.x < NE) g_cursor[threadIdx.x] = 0;
}

// ============================ launch ============================
extern "C" void kernel_launch(void* const* d_in, const int* in_sizes, int n_in,
                              void* d_out, int out_size)
{
    const int*   element = (const int*)d_in[0];
    const float* desc    = (const float*)d_in[1];
    const float* W1      = (const float*)d_in[2];
    const float* b1      = (const float*)d_in[3];
    const float* W2      = (const float*)d_in[4];
    const float* b2      = (const float*)d_in[5];
    float* out = (float*)d_out;
    int n = in_sizes[0];

    // staging 128*132*4 + A-f16 2*128*68*4 + B-f16 2048*16 = 67584+69632+32768
    const int DYN = 128 * LDS_F * 4 + 2 * 128 * 68 * 4 + 2048 * 16;  // 169984 B
    cudaFuncSetAttribute(gemm_kernel, cudaFuncAttributeMaxDynamicSharedMemorySize, DYN);

    assign_kernel<<<(n + 255) / 256, 256>>>(element, n);
    gemm_kernel<<<148, 512, DYN>>>(desc, W1, b1, W2, b2, out);
}

// round 14
// speedup vs baseline: 1.1758x; 1.1070x over previous
#include <cuda_runtime.h>
#include <cuda_fp16.h>
#include <cstdint>

#define NMAX 1000000
#define NE 4
#define DD 128
#define HH 128

// scratch (no allocation allowed -> device globals)
__device__ int g_cursor[NE];
__device__ int g_sorted[NE * NMAX];

// ============================ helpers ============================
__device__ __forceinline__ uint32_t smem_u32(const void* p){
    uint32_t r;
    asm("{ .reg .u64 t; cvta.to.shared.u64 t, %1; cvt.u32.u64 %0, t; }" : "=r"(r) : "l"(p));
    return r;
}
__device__ __forceinline__ uint32_t pack_f16x2(float lo, float hi){
    uint32_t r;
    asm("cvt.rn.f16x2.f32 %0, %1, %2;" : "=r"(r) : "f"(hi), "f"(lo));
    return r;
}
__device__ __forceinline__ void ldsm_x4(uint32_t& r0, uint32_t& r1, uint32_t& r2, uint32_t& r3,
                                        uint32_t addr){
    asm volatile("ldmatrix.sync.aligned.m8n8.x4.shared.b16 {%0,%1,%2,%3}, [%4];"
        : "=r"(r0), "=r"(r1), "=r"(r2), "=r"(r3) : "r"(addr));
}
__device__ __forceinline__ void mma_f16(float c[4],
                                        uint32_t a0, uint32_t a1, uint32_t a2, uint32_t a3,
                                        uint32_t b0, uint32_t b1){
    asm volatile(
        "mma.sync.aligned.m16n8k16.row.col.f32.f16.f16.f32 "
        "{%0,%1,%2,%3}, {%4,%5,%6,%7}, {%8,%9}, {%0,%1,%2,%3};"
        : "+f"(c[0]), "+f"(c[1]), "+f"(c[2]), "+f"(c[3])
        : "r"(a0), "r"(a1), "r"(a2), "r"(a3), "r"(b0), "r"(b1));
}

// ============================ bucketing ============================
__global__ void assign_kernel(const int* __restrict__ element, int n){
    __shared__ int wcnt[8][NE];
    __shared__ int woff[8][NE];
    __shared__ int bbase[NE];
    int tid = threadIdx.x, lane = tid & 31, w = tid >> 5;
    int i = blockIdx.x * 256 + tid;
    int e = (i < n) ? element[i] : -1;
    int rank = 0;
    #pragma unroll
    for (int ee = 0; ee < NE; ee++){
        unsigned m = __ballot_sync(0xFFFFFFFFu, e == ee);
        if (lane == 0) wcnt[w][ee] = __popc(m);
        if (e == ee) rank = __popc(m & ((1u << lane) - 1u));
    }
    __syncthreads();
    if (tid < NE){
        int s = 0;
        #pragma unroll
        for (int ww = 0; ww < 8; ww++){ int c = wcnt[ww][tid]; woff[ww][tid] = s; s += c; }
        bbase[tid] = s ? atomicAdd(&g_cursor[tid], s) : 0;
    }
    __syncthreads();
    if (e >= 0){
        int slot = bbase[e] + woff[w][e] + rank;
        g_sorted[e * NMAX + slot] = i;
    }
}

// ============================ main GEMM (fp16 MMA, fp32 accum) ============
__global__ __launch_bounds__(512, 1)
void gemm_kernel(const float* __restrict__ desc,
                 const float* __restrict__ W1,
                 const float* __restrict__ b1,
                 const float* __restrict__ W2,
                 const float* __restrict__ b2,
                 float* __restrict__ out)
{
    extern __shared__ float dyn[];
    uint32_t* sAh = (uint32_t*)dyn;                    // 2 x [128 x 68] f16x2 words
    float4*   sBq = (float4*)(sAh + 2 * 128 * 68);     // packed B f16 quads (2048 float4)

    __shared__ int   s_idx[2][128];
    __shared__ float s_part[2][128][4];
    __shared__ float s_b1e[HH], s_w2e[HH];
    __shared__ float s_b2e;

    const int tid  = threadIdx.x;
    const int wid  = tid >> 5;
    const int lane = tid & 31;
    const int l4   = lane >> 2;   // groupID (0..7)
    const int lm4  = lane & 3;    // threadID in group
    const int wm   = wid & 3;     // M group (32 rows)
    const int wn   = wid >> 2;    // N group (32 cols)
    const int seg  = tid & 31;    // 16B segment within a desc row (constant/thread)
    const int row0 = tid >> 5;    // base row; thread handles rows row0 + 16*i

    int cnt[NE], tstart[NE + 1];
    tstart[0] = 0;
    #pragma unroll
    for (int e = 0; e < NE; e++){
        cnt[e] = g_cursor[e];
        tstart[e + 1] = tstart[e] + ((cnt[e] + 127) >> 7);
    }
    const int total = tstart[NE];
    const int chunk = (total + (int)gridDim.x - 1) / (int)gridDim.x;
    const int t0 = blockIdx.x * chunk;
    const int t1 = min(total, t0 + chunk);

    if (t0 < t1) {
        auto expert_of = [&](int t){ int e = 0; while (t >= tstart[e + 1]) e++; return e; };

        auto load_expert = [&](int e){
            const float* W1e = W1 + (size_t)e * DD * HH;
            __half* sBh = (__half*)sBq;
            for (int v = tid; v < DD * HH; v += 512){
                int k = v >> 7, col = v & 127;       // W1[e][k][col]
                int ks = k >> 4, kk = k & 15;
                int lm4b = (kk & 7) >> 1, ddb = kk & 1, hb = kk >> 3;
                int wnb = col >> 5, rem = col & 31;
                int nbb = rem >> 3, l4b = rem & 7;
                int q = nbb >> 1, slot = (nbb & 1) * 2 + hb;
                int inner = ((l4b >> 1) << 3) + (lm4b << 1) + (l4b & 1);   // 0..31 bijection
                int idx128 = ((ks * 4 + wnb) * 2 + q) * 32 + inner;
                sBh[idx128 * 8 + slot * 2 + ddb] = __float2half_rn(W1e[v]);
            }
            if (tid < HH){
                s_b1e[tid] = b1[e * HH + tid];
                s_w2e[tid] = W2[e * HH + tid];
            }
            if (tid == 0) s_b2e = b2[e];
        };

        // synchronous gather+convert (prologue / expert switch only)
        auto gather_sync = [&](int t, int e, int buf){
            int trow = (t - tstart[e]) << 7;
            int rows = min(128, cnt[e] - trow);
            const int* bidx = g_sorted + e * NMAX + trow;
            if (tid < 128) s_idx[buf][tid] = (tid < rows) ? __ldg(bidx + tid) : -1;
            uint32_t* Ah = sAh + buf * (128 * 68);
            #pragma unroll
            for (int i = 0; i < 8; i++){
                int row = row0 + 16 * i;
                float4 f = make_float4(0.f, 0.f, 0.f, 0.f);
                if (row < rows){
                    int a = __ldg(bidx + row);
                    f = __ldg((const float4*)(desc + (size_t)a * DD + seg * 4));
                }
                uint2* dst = (uint2*)(Ah + row * 68 + seg * 2);
                *dst = make_uint2(pack_f16x2(f.x, f.y), pack_f16x2(f.z, f.w));
            }
        };

        int cur_e = expert_of(t0);
        load_expert(cur_e);
        gather_sync(t0, cur_e, 0);
        __syncthreads();

        // ldmatrix lane addressing: lane -> row (lane&15), k-half (lane>>4)
        const uint32_t aLane = (uint32_t)(((lane & 15) * 68 + ((lane >> 4) << 2)) << 2);
        const int innerB = ((l4 >> 1) << 3) + (lm4 << 1) + (l4 & 1);

        for (int t = t0; t < t1; ++t){
            const int buf = (t - t0) & 1;
            const int tn = t + 1;
            const bool have_next = tn < t1;
            const int e_next = have_next ? expert_of(tn) : -1;
            const bool same = have_next && (e_next == cur_e);

            // -------- pipeline stage 0: index loads for tile t+1 (8 regs) ------
            int idxr[8];
            if (same){
                int trow = (tn - tstart[cur_e]) << 7;
                int rows = min(128, cnt[cur_e] - trow);
                const int* bidx = g_sorted + cur_e * NMAX + trow;
                if (tid < 128) s_idx[buf ^ 1][tid] = (tid < rows) ? __ldg(bidx + tid) : -1;
                #pragma unroll
                for (int i = 0; i < 8; i++){
                    int row = row0 + 16 * i;
                    idxr[i] = (row < rows) ? __ldg(bidx + row) : -1;
                }
            }

            // ---- MMA: D[128x128] = A[128x128] @ W1^T (f16 operands) ----
            float acc[2][4][4];
            #pragma unroll
            for (int mb = 0; mb < 2; mb++)
                #pragma unroll
                for (int nb = 0; nb < 4; nb++)
                    #pragma unroll
                    for (int i = 0; i < 4; i++) acc[mb][nb][i] = 0.f;

            const uint32_t* Ah = sAh + buf * (128 * 68);
            const uint32_t aBase0 = smem_u32(Ah) + (uint32_t)((32 * wm * 68) << 2) + aLane;
            const uint32_t aBase1 = aBase0 + (uint32_t)((16 * 68) << 2);

            auto mma_step = [&](int ks){
                uint32_t a[2][4];
                ldsm_x4(a[0][0], a[0][1], a[0][2], a[0][3], aBase0 + ks * 32);
                ldsm_x4(a[1][0], a[1][1], a[1][2], a[1][3], aBase1 + ks * 32);
                uint32_t b[4][2];
                const float4* bp = sBq + ((ks * 4 + wn) * 2) * 32 + innerB;
                float4 bq0 = bp[0];
                float4 bq1 = bp[32];
                b[0][0] = __float_as_uint(bq0.x); b[0][1] = __float_as_uint(bq0.y);
                b[1][0] = __float_as_uint(bq0.z); b[1][1] = __float_as_uint(bq0.w);
                b[2][0] = __float_as_uint(bq1.x); b[2][1] = __float_as_uint(bq1.y);
                b[3][0] = __float_as_uint(bq1.z); b[3][1] = __float_as_uint(bq1.w);
                #pragma unroll
                for (int mb = 0; mb < 2; mb++)
                    #pragma unroll
                    for (int nb = 0; nb < 4; nb++)
                        mma_f16(acc[mb][nb], a[mb][0], a[mb][1], a[mb][2], a[mb][3],
                                b[nb][0], b[nb][1]);
            };

            mma_step(0); mma_step(1);

            // -------- stage 1: desc loads (32 regs, load-only window) ----------
            float4 g[8];
            if (same){
                #pragma unroll
                for (int i = 0; i < 8; i++){
                    g[i] = (idxr[i] >= 0)
                         ? __ldg((const float4*)(desc + (size_t)idxr[i] * DD + seg * 4))
                         : make_float4(0.f, 0.f, 0.f, 0.f);
                }
            }

            mma_step(2); mma_step(3);

            // -------- stage 2: convert + store straight into Ah[buf^1] --------
            if (same){
                uint32_t* Ah1 = sAh + (buf ^ 1) * (128 * 68);
                #pragma unroll
                for (int i = 0; i < 8; i++){
                    int row = row0 + 16 * i;
                    uint2* dst = (uint2*)(Ah1 + row * 68 + seg * 2);
                    *dst = make_uint2(pack_f16x2(g[i].x, g[i].y),
                                      pack_f16x2(g[i].z, g[i].w));
                }
            }

            mma_step(4); mma_step(5); mma_step(6); mma_step(7);

            // ---- epilogue: y[row] = sum_col relu(d + b1[col]) * w2[col] ----
            #pragma unroll
            for (int mb = 0; mb < 2; mb++){
                #pragma unroll
                for (int half = 0; half < 2; half++){
                    float p = 0.f;
                    #pragma unroll
                    for (int nb = 0; nb < 4; nb++){
                        int col = 32 * wn + 8 * nb + 2 * lm4;
                        float2 bb1 = *(const float2*)&s_b1e[col];
                        float2 ww2 = *(const float2*)&s_w2e[col];
                        float h0 = fmaxf(acc[mb][nb][2 * half + 0] + bb1.x, 0.f);
                        float h1 = fmaxf(acc[mb][nb][2 * half + 1] + bb1.y, 0.f);
                        p = fmaf(h0, ww2.x, p);
                        p = fmaf(h1, ww2.y, p);
                    }
                    p += __shfl_xor_sync(0xFFFFFFFFu, p, 1);
                    p += __shfl_xor_sync(0xFFFFFFFFu, p, 2);
                    if (lm4 == 0){
                        int row = 32 * wm + 16 * mb + 8 * half + l4;
                        s_part[buf][row][wn] = p;
                    }
                }
            }
            __syncthreads();   // publishes s_part[buf], s_idx[buf^1], Ah[buf^1]
            if (tid < 128){
                int a = s_idx[buf][tid];
                if (a >= 0)
                    out[a] = (s_part[buf][tid][0] + s_part[buf][tid][1])
                           + (s_part[buf][tid][2] + s_part[buf][tid][3]) + s_b2e;
            }
            // no trailing barrier: next tile uses the other s_part/s_idx buffer;
            // Ah hazards are ordered by the barrier above.

            if (have_next && !same){
                // expert switch (rare): all warps past MMA reads of sBq here
                __syncthreads();
                cur_e = e_next;
                load_expert(cur_e);
                gather_sync(tn, cur_e, buf ^ 1);
                __syncthreads();
            }
        }
    }

    // reset bucket cursors for the next replay (grid=148 is one wave, so all
    // CTAs snapshot g_cursor at entry before block 0 finishes)
    if (blockIdx.x == 0 && threadIdx.x < NE) g_cursor[threadIdx.x] = 0;
}

// ============================ launch ============================
extern "C" void kernel_launch(void* const* d_in, const int* in_sizes, int n_in,
                              void* d_out, int out_size)
{
    const int*   element = (const int*)d_in[0];
    const float* desc    = (const float*)d_in[1];
    const float* W1      = (const float*)d_in[2];
    const float* b1      = (const float*)d_in[3];
    const float* W2      = (const float*)d_in[4];
    const float* b2      = (const float*)d_in[5];
    float* out = (float*)d_out;
    int n = in_sizes[0];

    // A-f16 2*128*68*4 + B-f16 2048*16 = 69632 + 32768 = 102400 B
    const int DYN = 2 * 128 * 68 * 4 + 2048 * 16;
    cudaFuncSetAttribute(gemm_kernel, cudaFuncAttributeMaxDynamicSharedMemorySize, DYN);

    assign_kernel<<<(n + 255) / 256, 256>>>(element, n);
    gemm_kernel<<<148, 512, DYN>>>(desc, W1, b1, W2, b2, out);
}

// round 15
// speedup vs baseline: 1.2389x; 1.0537x over previous
#include <cuda_runtime.h>
#include <cuda_fp16.h>
#include <cstdint>

#define NMAX 1000000
#define NE 4
#define DD 128
#define HH 128

// scratch (no allocation allowed -> device globals)
__device__ int g_cursor[NE];
__device__ int g_sorted[NE * NMAX];

// ============================ helpers ============================
__device__ __forceinline__ uint32_t smem_u32(const void* p){
    uint32_t r;
    asm("{ .reg .u64 t; cvta.to.shared.u64 t, %1; cvt.u32.u64 %0, t; }" : "=r"(r) : "l"(p));
    return r;
}
__device__ __forceinline__ uint32_t pack_f16x2(float lo, float hi){
    uint32_t r;
    asm("cvt.rn.f16x2.f32 %0, %1, %2;" : "=r"(r) : "f"(hi), "f"(lo));
    return r;
}
__device__ __forceinline__ void ldsm_x4(uint32_t& r0, uint32_t& r1, uint32_t& r2, uint32_t& r3,
                                        uint32_t addr){
    asm volatile("ldmatrix.sync.aligned.m8n8.x4.shared.b16 {%0,%1,%2,%3}, [%4];"
        : "=r"(r0), "=r"(r1), "=r"(r2), "=r"(r3) : "r"(addr));
}
__device__ __forceinline__ void mma_f16(float c[4],
                                        uint32_t a0, uint32_t a1, uint32_t a2, uint32_t a3,
                                        uint32_t b0, uint32_t b1){
    asm volatile(
        "mma.sync.aligned.m16n8k16.row.col.f32.f16.f16.f32 "
        "{%0,%1,%2,%3}, {%4,%5,%6,%7}, {%8,%9}, {%0,%1,%2,%3};"
        : "+f"(c[0]), "+f"(c[1]), "+f"(c[2]), "+f"(c[3])
        : "r"(a0), "r"(a1), "r"(a2), "r"(a3), "r"(b0), "r"(b1));
}
#define GROUP_BAR(id) asm volatile("bar.sync %0, 128;" :: "r"(id) : "memory")

// ============================ bucketing ============================
__global__ void assign_kernel(const int* __restrict__ element, int n){
    __shared__ int wcnt[8][NE];
    __shared__ int woff[8][NE];
    __shared__ int bbase[NE];
    int tid = threadIdx.x, lane = tid & 31, w = tid >> 5;
    int i = blockIdx.x * 256 + tid;
    int e = (i < n) ? element[i] : -1;
    int rank = 0;
    #pragma unroll
    for (int ee = 0; ee < NE; ee++){
        unsigned m = __ballot_sync(0xFFFFFFFFu, e == ee);
        if (lane == 0) wcnt[w][ee] = __popc(m);
        if (e == ee) rank = __popc(m & ((1u << lane) - 1u));
    }
    __syncthreads();
    if (tid < NE){
        int s = 0;
        #pragma unroll
        for (int ww = 0; ww < 8; ww++){ int c = wcnt[ww][tid]; woff[ww][tid] = s; s += c; }
        bbase[tid] = s ? atomicAdd(&g_cursor[tid], s) : 0;
    }
    __syncthreads();
    if (e >= 0){
        int slot = bbase[e] + woff[w][e] + rank;
        g_sorted[e * NMAX + slot] = i;
    }
}

// ============================ main GEMM (fp16 MMA, fp32 accum) ============
// 16 warps = 4 row-groups (wm) x 4 col-warps (g=wn). All per-tile hazards are
// group-local -> per-tile sync is bar.sync(1+wm, 128), not __syncthreads.
__global__ __launch_bounds__(512, 1)
void gemm_kernel(const float* __restrict__ desc,
                 const float* __restrict__ W1,
                 const float* __restrict__ b1,
                 const float* __restrict__ W2,
                 const float* __restrict__ b2,
                 float* __restrict__ out)
{
    extern __shared__ float dyn[];
    uint32_t* sAh = (uint32_t*)dyn;                    // 2 x [128 x 68] f16x2 words
    float4*   sBq = (float4*)(sAh + 2 * 128 * 68);     // packed B f16 quads (2048 float4)

    __shared__ int   s_idx[2][128];
    __shared__ float s_part[2][128][4];
    __shared__ float s_b1e[HH], s_w2e[HH];
    __shared__ float s_b2e;

    const int tid  = threadIdx.x;
    const int wid  = tid >> 5;
    const int lane = tid & 31;
    const int l4   = lane >> 2;   // groupID (0..7)
    const int lm4  = lane & 3;    // threadID in group
    const int wm   = wid & 3;     // M group (32 rows)  == barrier group
    const int wn   = wid >> 2;    // N group (32 cols)  == g within group

    int cnt[NE], tstart[NE + 1];
    tstart[0] = 0;
    #pragma unroll
    for (int e = 0; e < NE; e++){
        cnt[e] = g_cursor[e];
        tstart[e + 1] = tstart[e] + ((cnt[e] + 127) >> 7);
    }
    const int total = tstart[NE];
    const int chunk = (total + (int)gridDim.x - 1) / (int)gridDim.x;
    const int t0 = blockIdx.x * chunk;
    const int t1 = min(total, t0 + chunk);

    if (t0 < t1) {
        auto expert_of = [&](int t){ int e = 0; while (t >= tstart[e + 1]) e++; return e; };

        auto load_expert = [&](int e){
            const float* W1e = W1 + (size_t)e * DD * HH;
            __half* sBh = (__half*)sBq;
            for (int v = tid; v < DD * HH; v += 512){
                int k = v >> 7, col = v & 127;       // W1[e][k][col]
                int ks = k >> 4, kk = k & 15;
                int lm4b = (kk & 7) >> 1, ddb = kk & 1, hb = kk >> 3;
                int wnb = col >> 5, rem = col & 31;
                int nbb = rem >> 3, l4b = rem & 7;
                int q = nbb >> 1, slot = (nbb & 1) * 2 + hb;
                int inner = ((l4b >> 1) << 3) + (lm4b << 1) + (l4b & 1);   // 0..31 bijection
                int idx128 = ((ks * 4 + wnb) * 2 + q) * 32 + inner;
                sBh[idx128 * 8 + slot * 2 + ddb] = __float2half_rn(W1e[v]);
            }
            if (tid < HH){
                s_b1e[tid] = b1[e * HH + tid];
                s_w2e[tid] = W2[e * HH + tid];
            }
            if (tid == 0) s_b2e = b2[e];
        };

        // group-mapped gather+convert, synchronous (prologue / expert switch)
        auto gather_sync = [&](int t, int e, int buf){
            int trow = (t - tstart[e]) << 7;
            int rows = min(128, cnt[e] - trow);
            const int* bidx = g_sorted + e * NMAX + trow;
            int myrow = 32 * wm + lane;
            int idxv = (myrow < rows) ? __ldg(bidx + myrow) : -1;
            if (wn == 0) s_idx[buf][myrow] = idxv;
            uint32_t* Ah = sAh + buf * (128 * 68);
            #pragma unroll
            for (int i = 0; i < 8; i++){
                int rlocal = wn + 4 * i;                 // row within group block
                int a = __shfl_sync(0xFFFFFFFFu, idxv, rlocal);
                float4 f = (a >= 0)
                         ? __ldg((const float4*)(desc + (size_t)a * DD + lane * 4))
                         : make_float4(0.f, 0.f, 0.f, 0.f);
                int row = 32 * wm + rlocal;
                uint2* dst = (uint2*)(Ah + row * 68 + lane * 2);
                *dst = make_uint2(pack_f16x2(f.x, f.y), pack_f16x2(f.z, f.w));
            }
        };

        int cur_e = expert_of(t0);
        load_expert(cur_e);
        gather_sync(t0, cur_e, 0);
        __syncthreads();

        // ldmatrix lane addressing: lane -> row (lane&15), k-half (lane>>4)
        const uint32_t aLane = (uint32_t)(((lane & 15) * 68 + ((lane >> 4) << 2)) << 2);
        const int innerB = ((l4 >> 1) << 3) + (lm4 << 1) + (l4 & 1);

        for (int t = t0; t < t1; ++t){
            const int buf = (t - t0) & 1;
            const int tn = t + 1;
            const bool have_next = tn < t1;
            const int e_next = have_next ? expert_of(tn) : -1;
            const bool same = have_next && (e_next == cur_e);

            // -------- stage 0: index load for tile t+1 (1 reg) ----------------
            int idxv = -1;
            if (same){
                int trow = (tn - tstart[cur_e]) << 7;
                int rows = min(128, cnt[cur_e] - trow);
                const int* bidx = g_sorted + cur_e * NMAX + trow;
                int myrow = 32 * wm + lane;
                idxv = (myrow < rows) ? __ldg(bidx + myrow) : -1;
                if (wn == 0) s_idx[buf ^ 1][myrow] = idxv;
            }

            // ---- MMA: D[128x128] = A[128x128] @ W1^T (f16 operands) ----
            float acc[2][4][4];
            #pragma unroll
            for (int mb = 0; mb < 2; mb++)
                #pragma unroll
                for (int nb = 0; nb < 4; nb++)
                    #pragma unroll
                    for (int i = 0; i < 4; i++) acc[mb][nb][i] = 0.f;

            const uint32_t* Ah = sAh + buf * (128 * 68);
            const uint32_t aBase0 = smem_u32(Ah) + (uint32_t)((32 * wm * 68) << 2) + aLane;
            const uint32_t aBase1 = aBase0 + (uint32_t)((16 * 68) << 2);

            auto mma_step = [&](int ks){
                uint32_t a[2][4];
                ldsm_x4(a[0][0], a[0][1], a[0][2], a[0][3], aBase0 + ks * 32);
                ldsm_x4(a[1][0], a[1][1], a[1][2], a[1][3], aBase1 + ks * 32);
                uint32_t b[4][2];
                const float4* bp = sBq + ((ks * 4 + wn) * 2) * 32 + innerB;
                float4 bq0 = bp[0];
                float4 bq1 = bp[32];
                b[0][0] = __float_as_uint(bq0.x); b[0][1] = __float_as_uint(bq0.y);
                b[1][0] = __float_as_uint(bq0.z); b[1][1] = __float_as_uint(bq0.w);
                b[2][0] = __float_as_uint(bq1.x); b[2][1] = __float_as_uint(bq1.y);
                b[3][0] = __float_as_uint(bq1.z); b[3][1] = __float_as_uint(bq1.w);
                #pragma unroll
                for (int mb = 0; mb < 2; mb++)
                    #pragma unroll
                    for (int nb = 0; nb < 4; nb++)
                        mma_f16(acc[mb][nb], a[mb][0], a[mb][1], a[mb][2], a[mb][3],
                                b[nb][0], b[nb][1]);
            };

            mma_step(0); mma_step(1);

            // -------- stage 1: desc loads (32 regs, load-only window) ----------
            float4 g[8];
            if (same){
                #pragma unroll
                for (int i = 0; i < 8; i++){
                    int a = __shfl_sync(0xFFFFFFFFu, idxv, wn + 4 * i);
                    g[i] = (a >= 0)
                         ? __ldg((const float4*)(desc + (size_t)a * DD + lane * 4))
                         : make_float4(0.f, 0.f, 0.f, 0.f);
                }
            }

            mma_step(2); mma_step(3);

            // -------- stage 2: convert + store straight into Ah[buf^1] --------
            if (same){
                uint32_t* Ah1 = sAh + (buf ^ 1) * (128 * 68);
                #pragma unroll
                for (int i = 0; i < 8; i++){
                    int row = 32 * wm + wn + 4 * i;
                    uint2* dst = (uint2*)(Ah1 + row * 68 + lane * 2);
                    *dst = make_uint2(pack_f16x2(g[i].x, g[i].y),
                                      pack_f16x2(g[i].z, g[i].w));
                }
            }

            mma_step(4); mma_step(5); mma_step(6); mma_step(7);

            // ---- epilogue: y[row] = sum_col relu(d + b1[col]) * w2[col] ----
            #pragma unroll
            for (int mb = 0; mb < 2; mb++){
                #pragma unroll
                for (int half = 0; half < 2; half++){
                    float p = 0.f;
                    #pragma unroll
                    for (int nb = 0; nb < 4; nb++){
                        int col = 32 * wn + 8 * nb + 2 * lm4;
                        float2 bb1 = *(const float2*)&s_b1e[col];
                        float2 ww2 = *(const float2*)&s_w2e[col];
                        float h0 = fmaxf(acc[mb][nb][2 * half + 0] + bb1.x, 0.f);
                        float h1 = fmaxf(acc[mb][nb][2 * half + 1] + bb1.y, 0.f);
                        p = fmaf(h0, ww2.x, p);
                        p = fmaf(h1, ww2.y, p);
                    }
                    p += __shfl_xor_sync(0xFFFFFFFFu, p, 1);
                    p += __shfl_xor_sync(0xFFFFFFFFu, p, 2);
                    if (lm4 == 0){
                        int row = 32 * wm + 16 * mb + 8 * half + l4;
                        s_part[buf][row][wn] = p;
                    }
                }
            }
            // group-local barrier: publishes this group's s_part[buf],
            // s_idx[buf^1] rows, and Ah[buf^1] rows (all group-private)
            GROUP_BAR(1 + wm);
            if (wn == 0){
                int row = 32 * wm + lane;
                int a = s_idx[buf][row];
                if (a >= 0)
                    out[a] = (s_part[buf][row][0] + s_part[buf][row][1])
                           + (s_part[buf][row][2] + s_part[buf][row][3]) + s_b2e;
            }
            // no trailing barrier: next tile uses the other s_part/s_idx buffer

            if (have_next && !same){
                // expert switch (rare, block-uniform): full barrier protects sBq
                __syncthreads();
                cur_e = e_next;
                load_expert(cur_e);
                gather_sync(tn, cur_e, buf ^ 1);
                __syncthreads();
            }
        }
    }

    // reset bucket cursors for the next replay (grid=148 is one wave, so all
    // CTAs snapshot g_cursor at entry before block 0 finishes)
    if (blockIdx.x == 0 && threadIdx.x < NE) g_cursor[threadIdx.x] = 0;
}

// ============================ launch ============================
extern "C" void kernel_launch(void* const* d_in, const int* in_sizes, int n_in,
                              void* d_out, int out_size)
{
    const int*   element = (const int*)d_in[0];
    const float* desc    = (const float*)d_in[1];
    const float* W1      = (const float*)d_in[2];
    const float* b1      = (const float*)d_in[3];
    const float* W2      = (const float*)d_in[4];
    const float* b2      = (const float*)d_in[5];
    float* out = (float*)d_out;
    int n = in_sizes[0];

    // A-f16 2*128*68*4 + B-f16 2048*16 = 69632 + 32768 = 102400 B
    const int DYN = 2 * 128 * 68 * 4 + 2048 * 16;
    cudaFuncSetAttribute(gemm_kernel, cudaFuncAttributeMaxDynamicSharedMemorySize, DYN);

    assign_kernel<<<(n + 255) / 256, 256>>>(element, n);
    gemm_kernel<<<148, 512, DYN>>>(desc, W1, b1, W2, b2, out);
}

// round 16
// speedup vs baseline: 1.2648x; 1.0209x over previous
#include <cuda_runtime.h>
#include <cuda_fp16.h>
#include <cstdint>

#define NMAX 1000000
#define NE 4
#define DD 128
#define HH 128

// scratch (no allocation allowed -> device globals)
__device__ int g_cursor[NE];
__device__ int g_sorted[NE * NMAX];

// ============================ helpers ============================
__device__ __forceinline__ uint32_t smem_u32(const void* p){
    uint32_t r;
    asm("{ .reg .u64 t; cvta.to.shared.u64 t, %1; cvt.u32.u64 %0, t; }" : "=r"(r) : "l"(p));
    return r;
}
__device__ __forceinline__ uint32_t pack_f16x2(float lo, float hi){
    uint32_t r;
    asm("cvt.rn.f16x2.f32 %0, %1, %2;" : "=r"(r) : "f"(hi), "f"(lo));
    return r;
}
__device__ __forceinline__ void ldsm_x4(uint32_t& r0, uint32_t& r1, uint32_t& r2, uint32_t& r3,
                                        uint32_t addr){
    asm volatile("ldmatrix.sync.aligned.m8n8.x4.shared.b16 {%0,%1,%2,%3}, [%4];"
        : "=r"(r0), "=r"(r1), "=r"(r2), "=r"(r3) : "r"(addr));
}
__device__ __forceinline__ void mma_f16(float c[4],
                                        uint32_t a0, uint32_t a1, uint32_t a2, uint32_t a3,
                                        uint32_t b0, uint32_t b1){
    asm volatile(
        "mma.sync.aligned.m16n8k16.row.col.f32.f16.f16.f32 "
        "{%0,%1,%2,%3}, {%4,%5,%6,%7}, {%8,%9}, {%0,%1,%2,%3};"
        : "+f"(c[0]), "+f"(c[1]), "+f"(c[2]), "+f"(c[3])
        : "r"(a0), "r"(a1), "r"(a2), "r"(a3), "r"(b0), "r"(b1));
}
#define GROUP_BAR(id) asm volatile("bar.sync %0, 128;" :: "r"(id) : "memory")

// ============================ bucketing ============================
__global__ void assign_kernel(const int* __restrict__ element, int n){
    __shared__ int wcnt[8][NE];
    __shared__ int woff[8][NE];
    __shared__ int bbase[NE];
    int tid = threadIdx.x, lane = tid & 31, w = tid >> 5;
    int i = blockIdx.x * 256 + tid;
    int e = (i < n) ? element[i] : -1;
    int rank = 0;
    #pragma unroll
    for (int ee = 0; ee < NE; ee++){
        unsigned m = __ballot_sync(0xFFFFFFFFu, e == ee);
        if (lane == 0) wcnt[w][ee] = __popc(m);
        if (e == ee) rank = __popc(m & ((1u << lane) - 1u));
    }
    __syncthreads();
    if (tid < NE){
        int s = 0;
        #pragma unroll
        for (int ww = 0; ww < 8; ww++){ int c = wcnt[ww][tid]; woff[ww][tid] = s; s += c; }
        bbase[tid] = s ? atomicAdd(&g_cursor[tid], s) : 0;
    }
    __syncthreads();
    if (e >= 0){
        int slot = bbase[e] + woff[w][e] + rank;
        g_sorted[e * NMAX + slot] = i;
    }
}

// ============================ main GEMM (fp16 MMA, fp32 accum) ============
// 16 warps = 4 row-groups (wm) x 4 col-warps (wn). KEY MAPPING: wm = wid>>2,
// wn = wid&3, so each barrier group spans all 4 SMSPs and each SMSP hosts one
// warp from each independently-drifting group -> phase-diverse issue per SMSP.
__global__ __launch_bounds__(512, 1)
void gemm_kernel(const float* __restrict__ desc,
                 const float* __restrict__ W1,
                 const float* __restrict__ b1,
                 const float* __restrict__ W2,
                 const float* __restrict__ b2,
                 float* __restrict__ out)
{
    extern __shared__ float dyn[];
    uint32_t* sAh = (uint32_t*)dyn;                    // 2 x [128 x 68] f16x2 words
    float4*   sBq = (float4*)(sAh + 2 * 128 * 68);     // packed B f16 quads (2048 float4)

    __shared__ int   s_idx[2][128];
    __shared__ float s_part[2][128][4];
    __shared__ float s_b1e[HH], s_w2e[HH];
    __shared__ float s_b2e;

    const int tid  = threadIdx.x;
    const int wid  = tid >> 5;
    const int lane = tid & 31;
    const int l4   = lane >> 2;   // groupID (0..7)
    const int lm4  = lane & 3;    // threadID in group
    const int wm   = wid >> 2;    // M group (32 rows) == barrier group (spans SMSPs)
    const int wn   = wid & 3;     // N group (32 cols) == SMSP id

    int cnt[NE], tstart[NE + 1];
    tstart[0] = 0;
    #pragma unroll
    for (int e = 0; e < NE; e++){
        cnt[e] = g_cursor[e];
        tstart[e + 1] = tstart[e] + ((cnt[e] + 127) >> 7);
    }
    const int total = tstart[NE];
    const int chunk = (total + (int)gridDim.x - 1) / (int)gridDim.x;
    const int t0 = blockIdx.x * chunk;
    const int t1 = min(total, t0 + chunk);

    if (t0 < t1) {
        auto expert_of = [&](int t){ int e = 0; while (t >= tstart[e + 1]) e++; return e; };

        auto load_expert = [&](int e){
            const float* W1e = W1 + (size_t)e * DD * HH;
            __half* sBh = (__half*)sBq;
            for (int v = tid; v < DD * HH; v += 512){
                int k = v >> 7, col = v & 127;       // W1[e][k][col]
                int ks = k >> 4, kk = k & 15;
                int lm4b = (kk & 7) >> 1, ddb = kk & 1, hb = kk >> 3;
                int wnb = col >> 5, rem = col & 31;
                int nbb = rem >> 3, l4b = rem & 7;
                int q = nbb >> 1, slot = (nbb & 1) * 2 + hb;
                int inner = ((l4b >> 1) << 3) + (lm4b << 1) + (l4b & 1);   // 0..31 bijection
                int idx128 = ((ks * 4 + wnb) * 2 + q) * 32 + inner;
                sBh[idx128 * 8 + slot * 2 + ddb] = __float2half_rn(W1e[v]);
            }
            if (tid < HH){
                s_b1e[tid] = b1[e * HH + tid];
                s_w2e[tid] = W2[e * HH + tid];
            }
            if (tid == 0) s_b2e = b2[e];
        };

        // group-mapped gather+convert, synchronous (prologue / expert switch)
        auto gather_sync = [&](int t, int e, int buf){
            int trow = (t - tstart[e]) << 7;
            int rows = min(128, cnt[e] - trow);
            const int* bidx = g_sorted + e * NMAX + trow;
            int myrow = 32 * wm + lane;
            int idxv = (myrow < rows) ? __ldg(bidx + myrow) : -1;
            if (wn == 0) s_idx[buf][myrow] = idxv;
            uint32_t* Ah = sAh + buf * (128 * 68);
            #pragma unroll
            for (int i = 0; i < 8; i++){
                int rlocal = wn + 4 * i;                 // row within group block
                int a = __shfl_sync(0xFFFFFFFFu, idxv, rlocal);
                float4 f = (a >= 0)
                         ? __ldg((const float4*)(desc + (size_t)a * DD + lane * 4))
                         : make_float4(0.f, 0.f, 0.f, 0.f);
                int row = 32 * wm + rlocal;
                uint2* dst = (uint2*)(Ah + row * 68 + lane * 2);
                *dst = make_uint2(pack_f16x2(f.x, f.y), pack_f16x2(f.z, f.w));
            }
        };

        int cur_e = expert_of(t0);
        load_expert(cur_e);
        gather_sync(t0, cur_e, 0);
        __syncthreads();

        // ldmatrix lane addressing: lane -> row (lane&15), k-half (lane>>4)
        const uint32_t aLane = (uint32_t)(((lane & 15) * 68 + ((lane >> 4) << 2)) << 2);
        const int innerB = ((l4 >> 1) << 3) + (lm4 << 1) + (l4 & 1);

        for (int t = t0; t < t1; ++t){
            const int buf = (t - t0) & 1;
            const int tn = t + 1;
            const bool have_next = tn < t1;
            const int e_next = have_next ? expert_of(tn) : -1;
            const bool same = have_next && (e_next == cur_e);

            // -------- stage 0: index load for tile t+1 (1 reg) ----------------
            int idxv = -1;
            if (same){
                int trow = (tn - tstart[cur_e]) << 7;
                int rows = min(128, cnt[cur_e] - trow);
                const int* bidx = g_sorted + cur_e * NMAX + trow;
                int myrow = 32 * wm + lane;
                idxv = (myrow < rows) ? __ldg(bidx + myrow) : -1;
                if (wn == 0) s_idx[buf ^ 1][myrow] = idxv;
            }

            // ---- MMA: D[128x128] = A[128x128] @ W1^T (f16 operands) ----
            float acc[2][4][4];
            #pragma unroll
            for (int mb = 0; mb < 2; mb++)
                #pragma unroll
                for (int nb = 0; nb < 4; nb++)
                    #pragma unroll
                    for (int i = 0; i < 4; i++) acc[mb][nb][i] = 0.f;

            const uint32_t* Ah = sAh + buf * (128 * 68);
            const uint32_t aBase0 = smem_u32(Ah) + (uint32_t)((32 * wm * 68) << 2) + aLane;
            const uint32_t aBase1 = aBase0 + (uint32_t)((16 * 68) << 2);

            auto mma_step = [&](int ks){
                uint32_t a[2][4];
                ldsm_x4(a[0][0], a[0][1], a[0][2], a[0][3], aBase0 + ks * 32);
                ldsm_x4(a[1][0], a[1][1], a[1][2], a[1][3], aBase1 + ks * 32);
                uint32_t b[4][2];
                const float4* bp = sBq + ((ks * 4 + wn) * 2) * 32 + innerB;
                float4 bq0 = bp[0];
                float4 bq1 = bp[32];
                b[0][0] = __float_as_uint(bq0.x); b[0][1] = __float_as_uint(bq0.y);
                b[1][0] = __float_as_uint(bq0.z); b[1][1] = __float_as_uint(bq0.w);
                b[2][0] = __float_as_uint(bq1.x); b[2][1] = __float_as_uint(bq1.y);
                b[3][0] = __float_as_uint(bq1.z); b[3][1] = __float_as_uint(bq1.w);
                #pragma unroll
                for (int mb = 0; mb < 2; mb++)
                    #pragma unroll
                    for (int nb = 0; nb < 4; nb++)
                        mma_f16(acc[mb][nb], a[mb][0], a[mb][1], a[mb][2], a[mb][3],
                                b[nb][0], b[nb][1]);
            };

            mma_step(0); mma_step(1);

            // -------- stage 1: desc loads (32 regs, load-only window) ----------
            float4 g[8];
            if (same){
                #pragma unroll
                for (int i = 0; i < 8; i++){
                    int a = __shfl_sync(0xFFFFFFFFu, idxv, wn + 4 * i);
                    g[i] = (a >= 0)
                         ? __ldg((const float4*)(desc + (size_t)a * DD + lane * 4))
                         : make_float4(0.f, 0.f, 0.f, 0.f);
                }
            }

            mma_step(2); mma_step(3);

            // -------- stage 2: convert + store straight into Ah[buf^1] --------
            if (same){
                uint32_t* Ah1 = sAh + (buf ^ 1) * (128 * 68);
                #pragma unroll
                for (int i = 0; i < 8; i++){
                    int row = 32 * wm + wn + 4 * i;
                    uint2* dst = (uint2*)(Ah1 + row * 68 + lane * 2);
                    *dst = make_uint2(pack_f16x2(g[i].x, g[i].y),
                                      pack_f16x2(g[i].z, g[i].w));
                }
            }

            mma_step(4); mma_step(5); mma_step(6); mma_step(7);

            // ---- epilogue: y[row] = sum_col relu(d + b1[col]) * w2[col] ----
            #pragma unroll
            for (int mb = 0; mb < 2; mb++){
                #pragma unroll
                for (int half = 0; half < 2; half++){
                    float p = 0.f;
                    #pragma unroll
                    for (int nb = 0; nb < 4; nb++){
                        int col = 32 * wn + 8 * nb + 2 * lm4;
                        float2 bb1 = *(const float2*)&s_b1e[col];
                        float2 ww2 = *(const float2*)&s_w2e[col];
                        float h0 = fmaxf(acc[mb][nb][2 * half + 0] + bb1.x, 0.f);
                        float h1 = fmaxf(acc[mb][nb][2 * half + 1] + bb1.y, 0.f);
                        p = fmaf(h0, ww2.x, p);
                        p = fmaf(h1, ww2.y, p);
                    }
                    p += __shfl_xor_sync(0xFFFFFFFFu, p, 1);
                    p += __shfl_xor_sync(0xFFFFFFFFu, p, 2);
                    if (lm4 == 0){
                        int row = 32 * wm + 16 * mb + 8 * half + l4;
                        s_part[buf][row][wn] = p;
                    }
                }
            }
            // group-local barrier: publishes this group's s_part[buf],
            // s_idx[buf^1] rows, and Ah[buf^1] rows (all group-private)
            GROUP_BAR(1 + wm);
            if (wn == 0){
                int row = 32 * wm + lane;
                int a = s_idx[buf][row];
                if (a >= 0)
                    out[a] = (s_part[buf][row][0] + s_part[buf][row][1])
                           + (s_part[buf][row][2] + s_part[buf][row][3]) + s_b2e;
            }
            // no trailing barrier: next tile uses the other s_part/s_idx buffer

            if (have_next && !same){
                // expert switch (rare, block-uniform): full barrier protects sBq
                __syncthreads();
                cur_e = e_next;
                load_expert(cur_e);
                gather_sync(tn, cur_e, buf ^ 1);
                __syncthreads();
            }
        }
    }

    // reset bucket cursors for the next replay (grid=148 is one wave, so all
    // CTAs snapshot g_cursor at entry before block 0 finishes)
    if (blockIdx.x == 0 && threadIdx.x < NE) g_cursor[threadIdx.x] = 0;
}

// ============================ launch ============================
extern "C" void kernel_launch(void* const* d_in, const int* in_sizes, int n_in,
                              void* d_out, int out_size)
{
    const int*   element = (const int*)d_in[0];
    const float* desc    = (const float*)d_in[1];
    const float* W1      = (const float*)d_in[2];
    const float* b1      = (const float*)d_in[3];
    const float* W2      = (const float*)d_in[4];
    const float* b2      = (const float*)d_in[5];
    float* out = (float*)d_out;
    int n = in_sizes[0];

    // A-f16 2*128*68*4 + B-f16 2048*16 = 69632 + 32768 = 102400 B
    const int DYN = 2 * 128 * 68 * 4 + 2048 * 16;
    cudaFuncSetAttribute(gemm_kernel, cudaFuncAttributeMaxDynamicSharedMemorySize, DYN);

    assign_kernel<<<(n + 255) / 256, 256>>>(element, n);
    gemm_kernel<<<148, 512, DYN>>>(desc, W1, b1, W2, b2, out);
}

// round 17
// speedup vs baseline: 1.3124x; 1.0376x over previous
#include <cuda_runtime.h>
#include <cuda_fp16.h>
#include <cstdint>

#define NMAX 1000000
#define NE 4
#define DD 128
#define HH 128

// scratch (no allocation allowed -> device globals)
__device__ int g_cursor[NE];
__device__ int g_sorted[NE * NMAX];

// ============================ helpers ============================
__device__ __forceinline__ uint32_t smem_u32(const void* p){
    uint32_t r;
    asm("{ .reg .u64 t; cvta.to.shared.u64 t, %1; cvt.u32.u64 %0, t; }" : "=r"(r) : "l"(p));
    return r;
}
__device__ __forceinline__ uint32_t pack_f16x2(float lo, float hi){
    uint32_t r;
    asm("cvt.rn.f16x2.f32 %0, %1, %2;" : "=r"(r) : "f"(hi), "f"(lo));
    return r;
}
__device__ __forceinline__ void ldsm_x4(uint32_t& r0, uint32_t& r1, uint32_t& r2, uint32_t& r3,
                                        uint32_t addr){
    asm volatile("ldmatrix.sync.aligned.m8n8.x4.shared.b16 {%0,%1,%2,%3}, [%4];"
        : "=r"(r0), "=r"(r1), "=r"(r2), "=r"(r3) : "r"(addr));
}
__device__ __forceinline__ void mma_f16(float c[4],
                                        uint32_t a0, uint32_t a1, uint32_t a2, uint32_t a3,
                                        uint32_t b0, uint32_t b1){
    asm volatile(
        "mma.sync.aligned.m16n8k16.row.col.f32.f16.f16.f32 "
        "{%0,%1,%2,%3}, {%4,%5,%6,%7}, {%8,%9}, {%0,%1,%2,%3};"
        : "+f"(c[0]), "+f"(c[1]), "+f"(c[2]), "+f"(c[3])
        : "r"(a0), "r"(a1), "r"(a2), "r"(a3), "r"(b0), "r"(b1));
}
#define GROUP_BAR(id) asm volatile("bar.sync %0, 128;" :: "r"(id) : "memory")

// ============================ bucketing ============================
__global__ void assign_kernel(const int* __restrict__ element, int n){
    __shared__ int wcnt[8][NE];
    __shared__ int woff[8][NE];
    __shared__ int bbase[NE];
    int tid = threadIdx.x, lane = tid & 31, w = tid >> 5;
    int i = blockIdx.x * 256 + tid;
    int e = (i < n) ? element[i] : -1;
    int rank = 0;
    #pragma unroll
    for (int ee = 0; ee < NE; ee++){
        unsigned m = __ballot_sync(0xFFFFFFFFu, e == ee);
        if (lane == 0) wcnt[w][ee] = __popc(m);
        if (e == ee) rank = __popc(m & ((1u << lane) - 1u));
    }
    __syncthreads();
    if (tid < NE){
        int s = 0;
        #pragma unroll
        for (int ww = 0; ww < 8; ww++){ int c = wcnt[ww][tid]; woff[ww][tid] = s; s += c; }
        bbase[tid] = s ? atomicAdd(&g_cursor[tid], s) : 0;
    }
    __syncthreads();
    if (e >= 0){
        int slot = bbase[e] + woff[w][e] + rank;
        g_sorted[e * NMAX + slot] = i;
    }
}

// ============================ main GEMM (fp16 MMA, fp32 accum) ============
// 16 warps = 4 row-groups (wm = wid>>2, spans all 4 SMSPs) x 4 col-warps
// (wn = wid&3). Per-tile sync is bar.sync(1+wm, 128). Global-load pipeline
// stages are spaced >577 cyc (DRAM latency) apart:
//   stage 0 (idx LDG)        before step 0
//   stage 1 (desc LDGs)      after step 2   (idx window ~3 steps)
//   stage 2 (convert+STS)    after step 6   (desc window ~4 steps)
__global__ __launch_bounds__(512, 1)
void gemm_kernel(const float* __restrict__ desc,
                 const float* __restrict__ W1,
                 const float* __restrict__ b1,
                 const float* __restrict__ W2,
                 const float* __restrict__ b2,
                 float* __restrict__ out)
{
    extern __shared__ float dyn[];
    uint32_t* sAh = (uint32_t*)dyn;                    // 2 x [128 x 68] f16x2 words
    float4*   sBq = (float4*)(sAh + 2 * 128 * 68);     // packed B f16 quads (2048 float4)

    __shared__ int   s_idx[2][128];
    __shared__ float s_part[2][128][4];
    __shared__ float s_b1e[HH], s_w2e[HH];
    __shared__ float s_b2e;

    const int tid  = threadIdx.x;
    const int wid  = tid >> 5;
    const int lane = tid & 31;
    const int l4   = lane >> 2;   // groupID (0..7)
    const int lm4  = lane & 3;    // threadID in group
    const int wm   = wid >> 2;    // M group (32 rows) == barrier group (spans SMSPs)
    const int wn   = wid & 3;     // N group (32 cols) == SMSP id

    int cnt[NE], tstart[NE + 1];
    tstart[0] = 0;
    #pragma unroll
    for (int e = 0; e < NE; e++){
        cnt[e] = g_cursor[e];
        tstart[e + 1] = tstart[e] + ((cnt[e] + 127) >> 7);
    }
    const int total = tstart[NE];
    const int chunk = (total + (int)gridDim.x - 1) / (int)gridDim.x;
    const int t0 = blockIdx.x * chunk;
    const int t1 = min(total, t0 + chunk);

    if (t0 < t1) {
        auto expert_of = [&](int t){ int e = 0; while (t >= tstart[e + 1]) e++; return e; };

        auto load_expert = [&](int e){
            const float* W1e = W1 + (size_t)e * DD * HH;
            __half* sBh = (__half*)sBq;
            for (int v = tid; v < DD * HH; v += 512){
                int k = v >> 7, col = v & 127;       // W1[e][k][col]
                int ks = k >> 4, kk = k & 15;
                int lm4b = (kk & 7) >> 1, ddb = kk & 1, hb = kk >> 3;
                int wnb = col >> 5, rem = col & 31;
                int nbb = rem >> 3, l4b = rem & 7;
                int q = nbb >> 1, slot = (nbb & 1) * 2 + hb;
                int inner = ((l4b >> 1) << 3) + (lm4b << 1) + (l4b & 1);   // 0..31 bijection
                int idx128 = ((ks * 4 + wnb) * 2 + q) * 32 + inner;
                sBh[idx128 * 8 + slot * 2 + ddb] = __float2half_rn(W1e[v]);
            }
            if (tid < HH){
                s_b1e[tid] = b1[e * HH + tid];
                s_w2e[tid] = W2[e * HH + tid];
            }
            if (tid == 0) s_b2e = b2[e];
        };

        // group-mapped gather+convert, synchronous (prologue / expert switch)
        auto gather_sync = [&](int t, int e, int buf){
            int trow = (t - tstart[e]) << 7;
            int rows = min(128, cnt[e] - trow);
            const int* bidx = g_sorted + e * NMAX + trow;
            int myrow = 32 * wm + lane;
            int idxv = (myrow < rows) ? __ldg(bidx + myrow) : -1;
            if (wn == 0) s_idx[buf][myrow] = idxv;
            uint32_t* Ah = sAh + buf * (128 * 68);
            #pragma unroll
            for (int i = 0; i < 8; i++){
                int rlocal = wn + 4 * i;                 // row within group block
                int a = __shfl_sync(0xFFFFFFFFu, idxv, rlocal);
                float4 f = (a >= 0)
                         ? __ldg((const float4*)(desc + (size_t)a * DD + lane * 4))
                         : make_float4(0.f, 0.f, 0.f, 0.f);
                int row = 32 * wm + rlocal;
                uint2* dst = (uint2*)(Ah + row * 68 + lane * 2);
                *dst = make_uint2(pack_f16x2(f.x, f.y), pack_f16x2(f.z, f.w));
            }
        };

        int cur_e = expert_of(t0);
        load_expert(cur_e);
        gather_sync(t0, cur_e, 0);
        __syncthreads();

        // ldmatrix lane addressing: lane -> row (lane&15), k-half (lane>>4)
        const uint32_t aLane = (uint32_t)(((lane & 15) * 68 + ((lane >> 4) << 2)) << 2);
        const int innerB = ((l4 >> 1) << 3) + (lm4 << 1) + (l4 & 1);

        for (int t = t0; t < t1; ++t){
            const int buf = (t - t0) & 1;
            const int tn = t + 1;
            const bool have_next = tn < t1;
            const int e_next = have_next ? expert_of(tn) : -1;
            const bool same = have_next && (e_next == cur_e);

            // -------- stage 0: index load for tile t+1 (1 reg) ----------------
            int idxv = -1;
            if (same){
                int trow = (tn - tstart[cur_e]) << 7;
                int rows = min(128, cnt[cur_e] - trow);
                const int* bidx = g_sorted + cur_e * NMAX + trow;
                int myrow = 32 * wm + lane;
                idxv = (myrow < rows) ? __ldg(bidx + myrow) : -1;
                if (wn == 0) s_idx[buf ^ 1][myrow] = idxv;
            }

            // ---- MMA: D[128x128] = A[128x128] @ W1^T (f16 operands) ----
            float acc[2][4][4];
            #pragma unroll
            for (int mb = 0; mb < 2; mb++)
                #pragma unroll
                for (int nb = 0; nb < 4; nb++)
                    #pragma unroll
                    for (int i = 0; i < 4; i++) acc[mb][nb][i] = 0.f;

            const uint32_t* Ah = sAh + buf * (128 * 68);
            const uint32_t aBase0 = smem_u32(Ah) + (uint32_t)((32 * wm * 68) << 2) + aLane;
            const uint32_t aBase1 = aBase0 + (uint32_t)((16 * 68) << 2);

            auto mma_step = [&](int ks){
                uint32_t a[2][4];
                ldsm_x4(a[0][0], a[0][1], a[0][2], a[0][3], aBase0 + ks * 32);
                ldsm_x4(a[1][0], a[1][1], a[1][2], a[1][3], aBase1 + ks * 32);
                uint32_t b[4][2];
                const float4* bp = sBq + ((ks * 4 + wn) * 2) * 32 + innerB;
                float4 bq0 = bp[0];
                float4 bq1 = bp[32];
                b[0][0] = __float_as_uint(bq0.x); b[0][1] = __float_as_uint(bq0.y);
                b[1][0] = __float_as_uint(bq0.z); b[1][1] = __float_as_uint(bq0.w);
                b[2][0] = __float_as_uint(bq1.x); b[2][1] = __float_as_uint(bq1.y);
                b[3][0] = __float_as_uint(bq1.z); b[3][1] = __float_as_uint(bq1.w);
                #pragma unroll
                for (int mb = 0; mb < 2; mb++)
                    #pragma unroll
                    for (int nb = 0; nb < 4; nb++)
                        mma_f16(acc[mb][nb], a[mb][0], a[mb][1], a[mb][2], a[mb][3],
                                b[nb][0], b[nb][1]);
            };

            mma_step(0); mma_step(1); mma_step(2);

            // -------- stage 1: desc loads (32 regs, load-only window) ----------
            // idx LDG has now had ~3 mma_steps to land.
            float4 g[8];
            if (same){
                #pragma unroll
                for (int i = 0; i < 8; i++){
                    int a = __shfl_sync(0xFFFFFFFFu, idxv, wn + 4 * i);
                    g[i] = (a >= 0)
                         ? __ldg((const float4*)(desc + (size_t)a * DD + lane * 4))
                         : make_float4(0.f, 0.f, 0.f, 0.f);
                }
            }

            mma_step(3); mma_step(4); mma_step(5); mma_step(6);

            // -------- stage 2: convert + store straight into Ah[buf^1] --------
            // desc LDGs have now had ~4 mma_steps (>577 cyc) to land.
            if (same){
                uint32_t* Ah1 = sAh + (buf ^ 1) * (128 * 68);
                #pragma unroll
                for (int i = 0; i < 8; i++){
                    int row = 32 * wm + wn + 4 * i;
                    uint2* dst = (uint2*)(Ah1 + row * 68 + lane * 2);
                    *dst = make_uint2(pack_f16x2(g[i].x, g[i].y),
                                      pack_f16x2(g[i].z, g[i].w));
                }
            }

            mma_step(7);

            // ---- epilogue: y[row] = sum_col relu(d + b1[col]) * w2[col] ----
            #pragma unroll
            for (int mb = 0; mb < 2; mb++){
                #pragma unroll
                for (int half = 0; half < 2; half++){
                    float p = 0.f;
                    #pragma unroll
                    for (int nb = 0; nb < 4; nb++){
                        int col = 32 * wn + 8 * nb + 2 * lm4;
                        float2 bb1 = *(const float2*)&s_b1e[col];
                        float2 ww2 = *(const float2*)&s_w2e[col];
                        float h0 = fmaxf(acc[mb][nb][2 * half + 0] + bb1.x, 0.f);
                        float h1 = fmaxf(acc[mb][nb][2 * half + 1] + bb1.y, 0.f);
                        p = fmaf(h0, ww2.x, p);
                        p = fmaf(h1, ww2.y, p);
                    }
                    p += __shfl_xor_sync(0xFFFFFFFFu, p, 1);
                    p += __shfl_xor_sync(0xFFFFFFFFu, p, 2);
                    if (lm4 == 0){
                        int row = 32 * wm + 16 * mb + 8 * half + l4;
                        s_part[buf][row][wn] = p;
                    }
                }
            }
            // group-local barrier: publishes this group's s_part[buf],
            // s_idx[buf^1] rows, and Ah[buf^1] rows (all group-private)
            GROUP_BAR(1 + wm);
            if (wn == 0){
                int row = 32 * wm + lane;
                int a = s_idx[buf][row];
                if (a >= 0)
                    out[a] = (s_part[buf][row][0] + s_part[buf][row][1])
                           + (s_part[buf][row][2] + s_part[buf][row][3]) + s_b2e;
            }
            // no trailing barrier: next tile uses the other s_part/s_idx buffer

            if (have_next && !same){
                // expert switch (rare, block-uniform): full barrier protects sBq
                __syncthreads();
                cur_e = e_next;
                load_expert(cur_e);
                gather_sync(tn, cur_e, buf ^ 1);
                __syncthreads();
            }
        }
    }

    // reset bucket cursors for the next replay (grid=148 is one wave, so all
    // CTAs snapshot g_cursor at entry before block 0 finishes)
    if (blockIdx.x == 0 && threadIdx.x < NE) g_cursor[threadIdx.x] = 0;
}

// ============================ launch ============================
extern "C" void kernel_launch(void* const* d_in, const int* in_sizes, int n_in,
                              void* d_out, int out_size)
{
    const int*   element = (const int*)d_in[0];
    const float* desc    = (const float*)d_in[1];
    const float* W1      = (const float*)d_in[2];
    const float* b1      = (const float*)d_in[3];
    const float* W2      = (const float*)d_in[4];
    const float* b2      = (const float*)d_in[5];
    float* out = (float*)d_out;
    int n = in_sizes[0];

    // A-f16 2*128*68*4 + B-f16 2048*16 = 69632 + 32768 = 102400 B
    const int DYN = 2 * 128 * 68 * 4 + 2048 * 16;
    cudaFuncSetAttribute(gemm_kernel, cudaFuncAttributeMaxDynamicSharedMemorySize, DYN);

    assign_kernel<<<(n + 255) / 256, 256>>>(element, n);
    gemm_kernel<<<148, 512, DYN>>>(desc, W1, b1, W2, b2, out);
}